// round 2
// baseline (speedup 1.0000x reference)
#include <cuda_runtime.h>
#include <cstdint>
#include <cstdio>

// Problem dims
#define B_  256
#define N_  128
#define D_  1024
#define H_  4096
#define K1_ 819
#define K2_ 3276
#define K1P 832     // K1 padded to multiple of 8 (and 4-float alignment)
#define K2P 3280    // K2 padded

// ---------------- scratch (device globals; no allocation allowed) ----------
__device__ __align__(256) float g_scores1[B_ * D_];
__device__ __align__(256) int   g_idx1[B_ * K1P];
__device__ __align__(256) float g_x1[(size_t)B_ * N_ * K1P];       // ~109 MB
__device__ __align__(256) float g_h[(size_t)B_ * N_ * H_];         // 512 MB
__device__ __align__(256) float g_scores2[B_ * H_];
__device__ __align__(256) int   g_idx2[B_ * K2P];
__device__ __align__(256) float g_h2[(size_t)B_ * N_ * K2P];       // ~430 MB
__device__ __align__(256) float g_W1p[(size_t)H_ * K1P];           // ~13.6 MB
__device__ __align__(256) float g_W2p[(size_t)D_ * K2P];           // ~13.4 MB

// ---------------- pack weights with zero K-padding --------------------------
__global__ void pack_kernel(const float* __restrict__ W, float* __restrict__ Wp,
                            int K, int KPAD, size_t total) {
    size_t i = (size_t)blockIdx.x * blockDim.x + threadIdx.x;
    if (i >= total) return;
    size_t r = i / KPAD;
    int k = (int)(i % KPAD);
    Wp[i] = (k < K) ? W[r * K + k] : 0.0f;
}

// ---------------- channel scores: scores[b,c] = sum_n x[b,n,c]*ws[n] + bs --
__global__ void scores_kernel(const float* __restrict__ x, const float* __restrict__ ws,
                              const float* __restrict__ bs, float* __restrict__ out,
                              int C) {
    __shared__ float w[N_];
    int tid = threadIdx.x;
    if (tid < N_) w[tid] = ws[tid];
    __syncthreads();
    int c = blockIdx.x * blockDim.x + tid;
    int b = blockIdx.y;
    const float* xp = x + (size_t)b * N_ * C + c;
    float s = 0.0f;
#pragma unroll 8
    for (int n = 0; n < N_; n++) s += xp[(size_t)n * C] * w[n];
    out[(size_t)b * C + c] = s + bs[0];
}

// ---------------- per-batch top-k via bitonic sort + order-preserving compact
// Matches jax.lax.top_k tie behavior (lower index wins), then indices ascending.
template <int C, int KKEEP, int KPAD>
__global__ __launch_bounds__(1024) void topk_kernel(const float* __restrict__ scores,
                                                    int* __restrict__ idx_out) {
    constexpr int E = C / 1024;
    __shared__ float ss[C];
    __shared__ int   si[C];
    __shared__ int   sc[1024];
    int b = blockIdx.x;
    int tid = threadIdx.x;

    for (int e = 0; e < E; e++) {
        int i = tid + e * 1024;
        ss[i] = scores[(size_t)b * C + i];
        si[i] = i;
    }
    __syncthreads();

    // Bitonic sort, "ascending by rank" where rank order = (score desc, idx asc)
    for (int k = 2; k <= C; k <<= 1) {
        for (int j = k >> 1; j > 0; j >>= 1) {
            for (int e = 0; e < E; e++) {
                int i = tid + e * 1024;
                int ixj = i ^ j;
                if (ixj > i) {
                    float s_i = ss[i], s_x = ss[ixj];
                    int   i_i = si[i], i_x = si[ixj];
                    // true if element at ixj ranks before element at i
                    bool before_x_i = (s_x > s_i) || (s_x == s_i && i_x < i_i);
                    bool up = ((i & k) == 0);
                    bool dosw = up ? before_x_i : !before_x_i;
                    if (dosw) {
                        ss[i] = s_x; ss[ixj] = s_i;
                        si[i] = i_x; si[ixj] = i_i;
                    }
                }
            }
            __syncthreads();
        }
    }

    // Flag selected channels (reuse ss storage as int flags)
    int* flag = (int*)ss;
    for (int e = 0; e < E; e++) flag[tid + e * 1024] = 0;
    __syncthreads();
    for (int e = 0; e < E; e++) {
        int p = tid + e * 1024;
        if (p < KKEEP) flag[si[p]] = 1;
    }
    __syncthreads();

    // Exclusive scan over per-thread contiguous chunks -> ascending index list
    int cnt = 0;
#pragma unroll
    for (int e = 0; e < E; e++) cnt += flag[tid * E + e];
    sc[tid] = cnt;
    __syncthreads();
    for (int off = 1; off < 1024; off <<= 1) {
        int t = (tid >= off) ? sc[tid - off] : 0;
        __syncthreads();
        sc[tid] += t;
        __syncthreads();
    }
    int base = sc[tid] - cnt;
    for (int e = 0; e < E; e++) {
        int c = tid * E + e;
        if (flag[c]) idx_out[(size_t)b * KPAD + (base++)] = c;
    }
}

// ---------------- gather selected channels with zero K-padding --------------
__global__ void gather_kernel(const float* __restrict__ src, const int* __restrict__ idx,
                              float* __restrict__ dst, int C, int KKEEP, int KPAD) {
    int k = blockIdx.x * blockDim.x + threadIdx.x;
    int bn = blockIdx.y;            // b*N_ + n
    int b = bn >> 7;                // N_ = 128
    if (k < KPAD) {
        float v = 0.0f;
        if (k < KKEEP) v = src[(size_t)bn * C + idx[(size_t)b * KPAD + k]];
        dst[(size_t)bn * KPAD + k] = v;
    }
}

// ---------------- fp32 SGEMM, NT layout (both operands K-contiguous) --------
// C[m, n] = sum_k A[m,k] * Bw[n,k] + bias[n]   (optional ReLU)
// Tiles: 128x128x8, 256 threads, 8x8 per thread.
__global__ __launch_bounds__(256) void gemm_nt(const float* __restrict__ A,
                                               const float* __restrict__ Bw,
                                               const float* __restrict__ bias,
                                               float* __restrict__ C,
                                               int Nd, int Kp, int relu) {
    __shared__ __align__(16) float As[8][132];
    __shared__ __align__(16) float Bs[8][132];

    int tid = threadIdx.x;
    int bx = blockIdx.x;   // N tile
    int by = blockIdx.y;   // M tile
    const float* Ab = A  + (size_t)by * 128 * Kp;
    const float* Bb = Bw + (size_t)bx * 128 * Kp;

    int lrow = tid >> 1;          // 0..127
    int lk   = (tid & 1) * 4;     // 0 or 4
    int tx = tid & 15, ty = tid >> 4;

    float acc[8][8];
#pragma unroll
    for (int i = 0; i < 8; i++)
#pragma unroll
        for (int j = 0; j < 8; j++) acc[i][j] = 0.0f;

    for (int k0 = 0; k0 < Kp; k0 += 8) {
        float4 a4 = *(const float4*)(Ab + (size_t)lrow * Kp + k0 + lk);
        float4 b4 = *(const float4*)(Bb + (size_t)lrow * Kp + k0 + lk);
        As[lk + 0][lrow] = a4.x; As[lk + 1][lrow] = a4.y;
        As[lk + 2][lrow] = a4.z; As[lk + 3][lrow] = a4.w;
        Bs[lk + 0][lrow] = b4.x; Bs[lk + 1][lrow] = b4.y;
        Bs[lk + 2][lrow] = b4.z; Bs[lk + 3][lrow] = b4.w;
        __syncthreads();

#pragma unroll
        for (int kk = 0; kk < 8; kk++) {
            float ra[8], rb[8];
            *(float4*)(ra)     = *(const float4*)(&As[kk][ty * 4]);
            *(float4*)(ra + 4) = *(const float4*)(&As[kk][64 + ty * 4]);
            *(float4*)(rb)     = *(const float4*)(&Bs[kk][tx * 4]);
            *(float4*)(rb + 4) = *(const float4*)(&Bs[kk][64 + tx * 4]);
#pragma unroll
            for (int i = 0; i < 8; i++)
#pragma unroll
                for (int j = 0; j < 8; j++) acc[i][j] += ra[i] * rb[j];
        }
        __syncthreads();
    }

    int row0 = by * 128, col0 = bx * 128;
    float4 bj0 = *(const float4*)(bias + col0 + tx * 4);
    float4 bj1 = *(const float4*)(bias + col0 + 64 + tx * 4);
#pragma unroll
    for (int i = 0; i < 8; i++) {
        int r = row0 + ((i < 4) ? (ty * 4 + i) : (64 + ty * 4 + i - 4));
        float4 v0, v1;
        v0.x = acc[i][0] + bj0.x; v0.y = acc[i][1] + bj0.y;
        v0.z = acc[i][2] + bj0.z; v0.w = acc[i][3] + bj0.w;
        v1.x = acc[i][4] + bj1.x; v1.y = acc[i][5] + bj1.y;
        v1.z = acc[i][6] + bj1.z; v1.w = acc[i][7] + bj1.w;
        if (relu) {
            v0.x = fmaxf(v0.x, 0.0f); v0.y = fmaxf(v0.y, 0.0f);
            v0.z = fmaxf(v0.z, 0.0f); v0.w = fmaxf(v0.w, 0.0f);
            v1.x = fmaxf(v1.x, 0.0f); v1.y = fmaxf(v1.y, 0.0f);
            v1.z = fmaxf(v1.z, 0.0f); v1.w = fmaxf(v1.w, 0.0f);
        }
        *(float4*)(C + (size_t)r * Nd + col0 + tx * 4)      = v0;
        *(float4*)(C + (size_t)r * Nd + col0 + 64 + tx * 4) = v1;
    }
}

// ---------------- launch ----------------------------------------------------
extern "C" void kernel_launch(void* const* d_in, const int* in_sizes, int n_in,
                              void* d_out, int out_size) {
    const float* x   = (const float*)d_in[0];
    const float* ws1 = (const float*)d_in[1];
    const float* bs1 = (const float*)d_in[2];
    const float* W1  = (const float*)d_in[3];
    const float* b1  = (const float*)d_in[4];
    const float* ws2 = (const float*)d_in[5];
    const float* bs2 = (const float*)d_in[6];
    const float* W2  = (const float*)d_in[7];
    const float* b2  = (const float*)d_in[8];
    float* out = (float*)d_out;

    float *scores1, *x1, *h, *scores2, *h2, *W1p, *W2p;
    int *idx1, *idx2;
    cudaGetSymbolAddress((void**)&scores1, g_scores1);
    cudaGetSymbolAddress((void**)&idx1,    g_idx1);
    cudaGetSymbolAddress((void**)&x1,      g_x1);
    cudaGetSymbolAddress((void**)&h,       g_h);
    cudaGetSymbolAddress((void**)&scores2, g_scores2);
    cudaGetSymbolAddress((void**)&idx2,    g_idx2);
    cudaGetSymbolAddress((void**)&h2,      g_h2);
    cudaGetSymbolAddress((void**)&W1p,     g_W1p);
    cudaGetSymbolAddress((void**)&W2p,     g_W2p);

    // Pack weights (zero K-padding) — deterministic, done every call
    {
        size_t t1 = (size_t)H_ * K1P;
        pack_kernel<<<(unsigned)((t1 + 255) / 256), 256>>>(W1, W1p, K1_, K1P, t1);
        size_t t2 = (size_t)D_ * K2P;
        pack_kernel<<<(unsigned)((t2 + 255) / 256), 256>>>(W2, W2p, K2_, K2P, t2);
    }

    // Stage 1: prune x (D -> K1)
    scores_kernel<<<dim3(D_ / 256, B_), 256>>>(x, ws1, bs1, scores1, D_);
    topk_kernel<D_, K1_, K1P><<<B_, 1024>>>(scores1, idx1);
    gather_kernel<<<dim3((K1P + 255) / 256, B_ * N_), 256>>>(x, idx1, x1, D_, K1_, K1P);

    // net1: h = relu(x1 @ W1^T + b1)
    gemm_nt<<<dim3(H_ / 128, (B_ * N_) / 128), 256>>>(x1, W1p, b1, h, H_, K1P, 1);

    // Stage 2: prune h (H -> K2)
    scores_kernel<<<dim3(H_ / 256, B_), 256>>>(h, ws2, bs2, scores2, H_);
    topk_kernel<H_, K2_, K2P><<<B_, 1024>>>(scores2, idx2);
    gather_kernel<<<dim3((K2P + 255) / 256, B_ * N_), 256>>>(h, idx2, h2, H_, K2_, K2P);

    // net2: out = h2 @ W2^T + b2
    gemm_nt<<<dim3(D_ / 128, (B_ * N_) / 128), 256>>>(h2, W2p, b2, out, D_, K2P, 0);
}

// round 5
// speedup vs baseline: 2.1292x; 2.1292x over previous
#include <cuda_runtime.h>
#include <cuda_bf16.h>
#include <cstdint>

// Problem dims
#define B_  256
#define N_  128
#define D_  1024
#define H_  4096
#define K1_ 819
#define K2_ 3276
#define K1P 832                 // padded keep-counts (multiple of 64)
#define K2P 3328
#define KPR1 (3*K1P)            // 2496  (K' = [hi|hi|lo] concat)
#define KPR2 (3*K2P)            // 9984
#define KC1  (KPR1/64)          // 39 K-chunks
#define KC2  (KPR2/64)          // 156

// ---------------- scratch (device globals; no allocation allowed) ----------
__device__ __align__(256) float          g_scores1[B_ * D_];
__device__ __align__(256) int            g_idx1[B_ * K1P];
__device__ __align__(256) __nv_bfloat16  g_x1[(size_t)B_ * N_ * KPR1];
__device__ __align__(256) float          g_h[(size_t)B_ * N_ * H_];
__device__ __align__(256) float          g_scores2[B_ * H_];
__device__ __align__(256) int            g_idx2[B_ * K2P];
__device__ __align__(256) __nv_bfloat16  g_h2[(size_t)B_ * N_ * KPR2];
__device__ __align__(256) __nv_bfloat16  g_W1p[(size_t)H_ * KPR1];
__device__ __align__(256) __nv_bfloat16  g_W2p[(size_t)D_ * KPR2];

// =================== helpers ================================================
__device__ __forceinline__ uint32_t smem_u32(const void* p) {
    uint32_t a;
    asm("{ .reg .u64 t; cvta.to.shared.u64 t, %1; cvt.u32.u64 %0, t; }" : "=r"(a) : "l"(p));
    return a;
}
__device__ __forceinline__ void cp16(uint32_t dst, const void* src) {
    asm volatile("cp.async.cg.shared.global [%0], [%1], 16;" :: "r"(dst), "l"(src) : "memory");
}
__device__ __forceinline__ uint32_t swz(uint32_t off) { return off ^ ((off >> 3) & 0x70); }

#define LDSM_X4(r, addr) \
    asm volatile("ldmatrix.sync.aligned.m8n8.x4.shared.b16 {%0,%1,%2,%3}, [%4];" \
        : "=r"((r)[0]), "=r"((r)[1]), "=r"((r)[2]), "=r"((r)[3]) : "r"(addr))

#define MMA16816(c, a, b) \
    asm volatile("mma.sync.aligned.m16n8k16.row.col.f32.bf16.bf16.f32 " \
        "{%0,%1,%2,%3}, {%4,%5,%6,%7}, {%8,%9}, {%0,%1,%2,%3};" \
        : "+f"((c)[0]), "+f"((c)[1]), "+f"((c)[2]), "+f"((c)[3]) \
        : "r"((a)[0]), "r"((a)[1]), "r"((a)[2]), "r"((a)[3]), "r"((b)[0]), "r"((b)[1]))

// =================== bf16 HMMA GEMM: C = A @ Bw^T + bias ====================
// A [M][kst] bf16, Bw [Nd][kst] bf16, C [M][Nd] f32. Tiles 128x128x64, 4 stages.
#define STAGES 4
#define STAGE_BYTES 32768       // (128+128) rows x 128B
#define GEMM_SMEM (STAGES * STAGE_BYTES)

__global__ __launch_bounds__(256, 1) void gemm_hmma(
    const __nv_bfloat16* __restrict__ A, const __nv_bfloat16* __restrict__ Bw,
    const float* __restrict__ bias, float* __restrict__ C,
    int Nd, int kchunks, int kst, int relu)
{
    extern __shared__ char smem[];
    const uint32_t sbase = smem_u32(smem);
    const int tid = threadIdx.x, wid = tid >> 5, lane = tid & 31;
    const int m0 = blockIdx.y * 128, n0 = blockIdx.x * 128;
    const int wm = (wid >> 2) * 64, wn = (wid & 3) * 32;

    float c[4][4][4];
#pragma unroll
    for (int i = 0; i < 4; i++)
#pragma unroll
        for (int j = 0; j < 4; j++)
#pragma unroll
            for (int q = 0; q < 4; q++) c[i][j][q] = 0.0f;

    // per-thread load pattern: 32 rows/wave x 8 threads/row(16B each)
    const int lr = tid >> 3;            // 0..31
    const int lcb = (tid & 7) * 16;     // 0..112

#define LOAD_CHUNK(k) do { \
    int _s = (k) & (STAGES - 1); \
    uint32_t _as = sbase + _s * STAGE_BYTES; \
    uint32_t _bs = _as + 16384; \
    const char* _Ag = (const char*)A + (size_t)(k) * 128 + lcb; \
    const char* _Bg = (const char*)Bw + (size_t)(k) * 128 + lcb; \
    _Ag += (size_t)(m0 + lr) * (size_t)kst * 2; \
    _Bg += (size_t)(n0 + lr) * (size_t)kst * 2; \
    uint32_t _d = swz((uint32_t)(lr * 128 + lcb)); \
    size_t _rstep = (size_t)kst * 64;  /* 32 rows in bytes */ \
    cp16(_as + _d,          _Ag); \
    cp16(_as + _d + 0x1000, _Ag + _rstep); \
    cp16(_as + _d + 0x2000, _Ag + 2 * _rstep); \
    cp16(_as + _d + 0x3000, _Ag + 3 * _rstep); \
    cp16(_bs + _d,          _Bg); \
    cp16(_bs + _d + 0x1000, _Bg + _rstep); \
    cp16(_bs + _d + 0x2000, _Bg + 2 * _rstep); \
    cp16(_bs + _d + 0x3000, _Bg + 3 * _rstep); \
} while (0)
    // note: 32 rows x 128B = 4096B = 0x1000, and swz only touches bits<10 so
    // adding 0x1000 keeps the swizzle pattern of the row-within-32 block.

    // prologue
    for (int k = 0; k < STAGES - 1 && k < kchunks; k++) {
        LOAD_CHUNK(k);
        asm volatile("cp.async.commit_group;" ::: "memory");
    }

    for (int k = 0; k < kchunks; k++) {
        asm volatile("cp.async.wait_group %0;" :: "n"(STAGES - 2) : "memory");
        __syncthreads();

        if (k + STAGES - 1 < kchunks) LOAD_CHUNK(k + STAGES - 1);
        asm volatile("cp.async.commit_group;" ::: "memory");

        const int st = k & (STAGES - 1);
        const uint32_t as = sbase + st * STAGE_BYTES;
        const uint32_t bs = as + 16384;
#pragma unroll
        for (int ks = 0; ks < 4; ks++) {
            uint32_t a[4][4], b[4][2];
            const int cb = ks * 32 + ((lane >> 4) << 4);
#pragma unroll
            for (int mt = 0; mt < 4; mt++) {
                uint32_t off = (uint32_t)((wm + mt * 16 + (lane & 15)) * 128 + cb);
                LDSM_X4(a[mt], as + swz(off));
            }
#pragma unroll
            for (int p = 0; p < 2; p++) {
                uint32_t t[4];
                uint32_t off = (uint32_t)((wn + p * 16 + (lane & 15)) * 128 + cb);
                LDSM_X4(t, bs + swz(off));
                b[2 * p][0] = t[0]; b[2 * p][1] = t[2];
                b[2 * p + 1][0] = t[1]; b[2 * p + 1][1] = t[3];
            }
#pragma unroll
            for (int mt = 0; mt < 4; mt++)
#pragma unroll
                for (int nt = 0; nt < 4; nt++)
                    MMA16816(c[mt][nt], a[mt], b[nt]);
        }
        __syncthreads();
    }

    // epilogue: frag (mt,nt): rows wm+mt*16+lane/4 (+8), cols wn+nt*8+2*(lane%4)
#pragma unroll
    for (int mt = 0; mt < 4; mt++) {
        int row = m0 + wm + mt * 16 + (lane >> 2);
#pragma unroll
        for (int nt = 0; nt < 4; nt++) {
            int col = n0 + wn + nt * 8 + 2 * (lane & 3);
            float2 bv = *(const float2*)(bias + col);
            float2 v0 = make_float2(c[mt][nt][0] + bv.x, c[mt][nt][1] + bv.y);
            float2 v1 = make_float2(c[mt][nt][2] + bv.x, c[mt][nt][3] + bv.y);
            if (relu) {
                v0.x = fmaxf(v0.x, 0.0f); v0.y = fmaxf(v0.y, 0.0f);
                v1.x = fmaxf(v1.x, 0.0f); v1.y = fmaxf(v1.y, 0.0f);
            }
            *(float2*)(C + (size_t)row * Nd + col) = v0;
            *(float2*)(C + (size_t)(row + 8) * Nd + col) = v1;
        }
    }
}

// =================== scores: s[b,c] = sum_n x[b,n,c]*ws[n] + bs =============
__global__ void scores_kernel(const float* __restrict__ x, const float* __restrict__ ws,
                              const float* __restrict__ bs, float* __restrict__ out, int C) {
    __shared__ float w[N_];
    int tid = threadIdx.x;
    if (tid < N_) w[tid] = ws[tid];
    __syncthreads();
    int c = blockIdx.x * blockDim.x + tid;
    int b = blockIdx.y;
    const float* xp = x + (size_t)b * N_ * C + c;
    float s = 0.0f;
#pragma unroll 8
    for (int n = 0; n < N_; n++) s += xp[(size_t)n * C] * w[n];
    out[(size_t)b * C + c] = s + bs[0];
}

// =================== top-k (jax.lax.top_k tie semantics) ====================
template <int C, int KKEEP, int KPAD>
__global__ __launch_bounds__(1024) void topk_kernel(const float* __restrict__ scores,
                                                    int* __restrict__ idx_out) {
    constexpr int E = C / 1024;
    __shared__ float ss[C];
    __shared__ int   si[C];
    __shared__ int   sc[1024];
    int b = blockIdx.x, tid = threadIdx.x;
    for (int e = 0; e < E; e++) { int i = tid + e * 1024; ss[i] = scores[(size_t)b * C + i]; si[i] = i; }
    __syncthreads();
    for (int k = 2; k <= C; k <<= 1)
        for (int j = k >> 1; j > 0; j >>= 1) {
            for (int e = 0; e < E; e++) {
                int i = tid + e * 1024, ixj = i ^ j;
                if (ixj > i) {
                    float s_i = ss[i], s_x = ss[ixj];
                    int   i_i = si[i], i_x = si[ixj];
                    bool bx = (s_x > s_i) || (s_x == s_i && i_x < i_i);
                    bool dosw = ((i & k) == 0) ? bx : !bx;
                    if (dosw) { ss[i] = s_x; ss[ixj] = s_i; si[i] = i_x; si[ixj] = i_i; }
                }
            }
            __syncthreads();
        }
    int* flag = (int*)ss;
    for (int e = 0; e < E; e++) flag[tid + e * 1024] = 0;
    __syncthreads();
    for (int e = 0; e < E; e++) { int p = tid + e * 1024; if (p < KKEEP) flag[si[p]] = 1; }
    __syncthreads();
    int cnt = 0;
#pragma unroll
    for (int e = 0; e < E; e++) cnt += flag[tid * E + e];
    sc[tid] = cnt;
    __syncthreads();
    for (int off = 1; off < 1024; off <<= 1) {
        int t = (tid >= off) ? sc[tid - off] : 0;
        __syncthreads();
        sc[tid] += t;
        __syncthreads();
    }
    int base = sc[tid] - cnt;
    for (int e = 0; e < E; e++) { int c = tid * E + e; if (flag[c]) idx_out[(size_t)b * KPAD + (base++)] = c; }
}

// ======= gather fp32 -> bf16 hi/lo sections A' = [hi | hi | lo] =============
__global__ void gather_split_kernel(const float* __restrict__ src, const int* __restrict__ idx,
                                    __nv_bfloat16* __restrict__ dst, int C, int KKEEP, int KP) {
    int k = blockIdx.x * blockDim.x + threadIdx.x;
    int bn = blockIdx.y;
    int b = bn >> 7;
    if (k >= KP) return;
    float v = 0.0f;
    if (k < KKEEP) v = src[(size_t)bn * C + idx[(size_t)b * KP + k]];
    __nv_bfloat16 hi = __float2bfloat16_rn(v);
    __nv_bfloat16 lo = __float2bfloat16_rn(v - __bfloat162float(hi));
    size_t base = (size_t)bn * (3 * (size_t)KP);
    dst[base + k] = hi;
    dst[base + KP + k] = hi;
    dst[base + 2 * (size_t)KP + k] = lo;
}

// ======= weight pack fp32 -> bf16 sections B' = [hi | lo | hi] ==============
__global__ void pack_split_kernel(const float* __restrict__ W, __nv_bfloat16* __restrict__ Wp,
                                  int K, int KP) {
    int k = blockIdx.x * blockDim.x + threadIdx.x;
    int r = blockIdx.y;
    if (k >= KP) return;
    float v = (k < K) ? W[(size_t)r * K + k] : 0.0f;
    __nv_bfloat16 hi = __float2bfloat16_rn(v);
    __nv_bfloat16 lo = __float2bfloat16_rn(v - __bfloat162float(hi));
    size_t base = (size_t)r * (3 * (size_t)KP);
    Wp[base + k] = hi;
    Wp[base + KP + k] = lo;
    Wp[base + 2 * (size_t)KP + k] = hi;
}

// =================== host side ==============================================
extern "C" void kernel_launch(void* const* d_in, const int* in_sizes, int n_in,
                              void* d_out, int out_size) {
    const float* x   = (const float*)d_in[0];
    const float* ws1 = (const float*)d_in[1];
    const float* bs1 = (const float*)d_in[2];
    const float* W1  = (const float*)d_in[3];
    const float* b1  = (const float*)d_in[4];
    const float* ws2 = (const float*)d_in[5];
    const float* bs2 = (const float*)d_in[6];
    const float* W2  = (const float*)d_in[7];
    const float* b2  = (const float*)d_in[8];
    float* out = (float*)d_out;

    float *scores1, *h, *scores2;
    __nv_bfloat16 *x1, *h2, *W1p, *W2p;
    int *idx1, *idx2;
    cudaGetSymbolAddress((void**)&scores1, g_scores1);
    cudaGetSymbolAddress((void**)&idx1,    g_idx1);
    cudaGetSymbolAddress((void**)&x1,      g_x1);
    cudaGetSymbolAddress((void**)&h,       g_h);
    cudaGetSymbolAddress((void**)&scores2, g_scores2);
    cudaGetSymbolAddress((void**)&idx2,    g_idx2);
    cudaGetSymbolAddress((void**)&h2,      g_h2);
    cudaGetSymbolAddress((void**)&W1p,     g_W1p);
    cudaGetSymbolAddress((void**)&W2p,     g_W2p);

    cudaFuncSetAttribute(gemm_hmma, cudaFuncAttributeMaxDynamicSharedMemorySize, GEMM_SMEM);

    // weight packs (bf16 hi/lo sections)
    pack_split_kernel<<<dim3((K1P + 255) / 256, H_), 256>>>(W1, W1p, K1_, K1P);
    pack_split_kernel<<<dim3((K2P + 255) / 256, D_), 256>>>(W2, W2p, K2_, K2P);

    // stage 1: prune x (D -> K1)
    scores_kernel<<<dim3(D_ / 256, B_), 256>>>(x, ws1, bs1, scores1, D_);
    topk_kernel<D_, K1_, K1P><<<B_, 1024>>>(scores1, idx1);
    gather_split_kernel<<<dim3((K1P + 255) / 256, B_ * N_), 256>>>(x, idx1, x1, D_, K1_, K1P);

    // net1: h = relu(x1 @ W1^T + b1)   [bf16 HMMA, K'=2496]
    gemm_hmma<<<dim3(H_ / 128, (B_ * N_) / 128), 256, GEMM_SMEM>>>(
        x1, W1p, b1, h, H_, KC1, KPR1, 1);

    // stage 2: prune h (H -> K2)
    scores_kernel<<<dim3(H_ / 256, B_), 256>>>(h, ws2, bs2, scores2, H_);
    topk_kernel<H_, K2_, K2P><<<B_, 1024>>>(scores2, idx2);
    gather_split_kernel<<<dim3((K2P + 255) / 256, B_ * N_), 256>>>(h, idx2, h2, H_, K2_, K2P);

    // net2: out = h2 @ W2^T + b2   [bf16 HMMA, K'=9984]
    gemm_hmma<<<dim3(D_ / 128, (B_ * N_) / 128), 256, GEMM_SMEM>>>(
        h2, W2p, b2, out, D_, KC2, KPR2, 0);
}

// round 7
// speedup vs baseline: 2.2411x; 1.0526x over previous
#include <cuda_runtime.h>
#include <cuda_fp16.h>
#include <cstdint>

// Problem dims
#define B_  256
#define N_  128
#define D_  1024
#define H_  4096
#define K1_ 819
#define K2_ 3276
#define K1P 832                 // padded keep-counts (multiple of 64)
#define K2P 3328
#define NCK1 (K1P/64)           // 13 chunk-cols per section
#define NCK2 (K2P/64)           // 52
#define KCH1 (3*NCK1)           // 39 total K-chunks (3-term)
#define KCH2 (2*NCK2)           // 104 (2-term)

// ---------------- scratch (device globals; no allocation allowed) ----------
__device__ __align__(256) float  g_scores1[B_ * D_];
__device__ __align__(256) int    g_idx1[B_ * K1P];
__device__ __align__(256) __half g_x1[(size_t)B_ * N_ * 2 * K1P];  // [hi|lo] ~109MB
__device__ __align__(256) __half g_h[(size_t)B_ * N_ * H_];        // hi plane ~268MB
__device__ __align__(256) float  g_scores2[B_ * H_];
__device__ __align__(256) int    g_idx2[B_ * K2P];
__device__ __align__(256) __half g_h2[(size_t)B_ * N_ * K2P];      // hi only ~218MB
__device__ __align__(256) __half g_W1p[(size_t)H_ * 2 * K1P];      // [hi|lo]
__device__ __align__(256) __half g_W2p[(size_t)D_ * 2 * K2P];      // [hi|lo]

// =================== helpers ================================================
__device__ __forceinline__ uint32_t smem_u32(const void* p) {
    uint32_t a;
    asm("{ .reg .u64 t; cvta.to.shared.u64 t, %1; cvt.u32.u64 %0, t; }" : "=r"(a) : "l"(p));
    return a;
}
__device__ __forceinline__ void cp16(uint32_t dst, const void* src) {
    asm volatile("cp.async.cg.shared.global [%0], [%1], 16;" :: "r"(dst), "l"(src) : "memory");
}
__device__ __forceinline__ uint32_t swz(uint32_t off) { return off ^ ((off >> 3) & 0x70); }

#define LDSM_X4(r, addr) \
    asm volatile("ldmatrix.sync.aligned.m8n8.x4.shared.b16 {%0,%1,%2,%3}, [%4];" \
        : "=r"((r)[0]), "=r"((r)[1]), "=r"((r)[2]), "=r"((r)[3]) : "r"(addr))

#define MMA16816(c, a, b) \
    asm volatile("mma.sync.aligned.m16n8k16.row.col.f32.f16.f16.f32 " \
        "{%0,%1,%2,%3}, {%4,%5,%6,%7}, {%8,%9}, {%0,%1,%2,%3};" \
        : "+f"((c)[0]), "+f"((c)[1]), "+f"((c)[2]), "+f"((c)[3]) \
        : "r"((a)[0]), "r"((a)[1]), "r"((a)[2]), "r"((b)[0]), "r"((b)[1]))

// fix: MMA macro needs all 4 a regs
#undef MMA16816
#define MMA16816(c, a, b) \
    asm volatile("mma.sync.aligned.m16n8k16.row.col.f32.f16.f16.f32 " \
        "{%0,%1,%2,%3}, {%4,%5,%6,%7}, {%8,%9}, {%0,%1,%2,%3};" \
        : "+f"((c)[0]), "+f"((c)[1]), "+f"((c)[2]), "+f"((c)[3]) \
        : "r"((a)[0]), "r"((a)[1]), "r"((a)[2]), "r"((a)[3]), "r"((b)[0]), "r"((b)[1]))

// =================== fp16 HMMA GEMM with sectioned-K mapping ================
// A [M][kstA] f16, Bw [Nd][kstB] f16. Tiles 128x128x64, 4 stages, 256 thr.
// mode 1 (3-term): t=k/ncol: (t0) hiA*hiB (t1) hiA*loB (t2) loA*hiB
// mode 2 (2-term): t=k/ncol: (t0) hiA*hiB (t1) hiA*loB      (A has hi only)
// EPI 0: Cout = acc + bias (fp32)
// EPI 1: v=relu(acc+bias); Hout=half(v); scores_out[b][col]=sum_n ws2[n]*v+bs2
#define STAGES 4
#define STAGE_BYTES 32768
#define GEMM_SMEM (STAGES * STAGE_BYTES)

template <int EPI>
__global__ __launch_bounds__(256, 1) void gemm_hmma(
    const __half* __restrict__ A, const __half* __restrict__ Bw,
    const float* __restrict__ bias, float* __restrict__ Cout,
    __half* __restrict__ Hout, float* __restrict__ scores_out,
    const float* __restrict__ ws2, const float* __restrict__ bs2,
    int Nd, int kchunks, int ncol, int mode, int kstA, int kstB)
{
    extern __shared__ char smem[];
    const uint32_t sbase = smem_u32(smem);
    const int tid = threadIdx.x, wid = tid >> 5, lane = tid & 31;
    const int m0 = blockIdx.y * 128, n0 = blockIdx.x * 128;
    const int wm = (wid >> 2) * 64, wn = (wid & 3) * 32;

    float c[4][4][4];
#pragma unroll
    for (int i = 0; i < 4; i++)
#pragma unroll
        for (int j = 0; j < 4; j++)
#pragma unroll
            for (int q = 0; q < 4; q++) c[i][j][q] = 0.0f;

    const int lr = tid >> 3;            // 0..31
    const int lcb = (tid & 7) * 16;     // 0..112

#define LOAD_CHUNK(k) do { \
    int _t = (k) / ncol, _kk = (k) - _t * ncol; \
    int _ka, _kb; \
    if (mode == 1) { _ka = (_t == 2) ? ncol + _kk : _kk; _kb = (_t == 1) ? ncol + _kk : _kk; } \
    else           { _ka = _kk; _kb = (k); } \
    int _s = (k) & (STAGES - 1); \
    uint32_t _as = sbase + _s * STAGE_BYTES; \
    uint32_t _bs = _as + 16384; \
    const char* _Ag = (const char*)A + (size_t)_ka * 128 + lcb + (size_t)(m0 + lr) * (size_t)kstA * 2; \
    const char* _Bg = (const char*)Bw + (size_t)_kb * 128 + lcb + (size_t)(n0 + lr) * (size_t)kstB * 2; \
    uint32_t _d = swz((uint32_t)(lr * 128 + lcb)); \
    size_t _ra = (size_t)kstA * 64, _rb = (size_t)kstB * 64; \
    cp16(_as + _d,          _Ag); \
    cp16(_as + _d + 0x1000, _Ag + _ra); \
    cp16(_as + _d + 0x2000, _Ag + 2 * _ra); \
    cp16(_as + _d + 0x3000, _Ag + 3 * _ra); \
    cp16(_bs + _d,          _Bg); \
    cp16(_bs + _d + 0x1000, _Bg + _rb); \
    cp16(_bs + _d + 0x2000, _Bg + 2 * _rb); \
    cp16(_bs + _d + 0x3000, _Bg + 3 * _rb); \
} while (0)

    for (int k = 0; k < STAGES - 1 && k < kchunks; k++) {
        LOAD_CHUNK(k);
        asm volatile("cp.async.commit_group;" ::: "memory");
    }

    for (int k = 0; k < kchunks; k++) {
        asm volatile("cp.async.wait_group %0;" :: "n"(STAGES - 2) : "memory");
        __syncthreads();

        if (k + STAGES - 1 < kchunks) LOAD_CHUNK(k + STAGES - 1);
        asm volatile("cp.async.commit_group;" ::: "memory");

        const int st = k & (STAGES - 1);
        const uint32_t as = sbase + st * STAGE_BYTES;
        const uint32_t bs = as + 16384;
#pragma unroll
        for (int ks = 0; ks < 4; ks++) {
            uint32_t a[4][4], b[4][2];
            const int cb = ks * 32 + ((lane >> 4) << 4);
#pragma unroll
            for (int mt = 0; mt < 4; mt++) {
                uint32_t off = (uint32_t)((wm + mt * 16 + (lane & 15)) * 128 + cb);
                LDSM_X4(a[mt], as + swz(off));
            }
#pragma unroll
            for (int p = 0; p < 2; p++) {
                uint32_t t[4];
                uint32_t off = (uint32_t)((wn + p * 16 + (lane & 15)) * 128 + cb);
                LDSM_X4(t, bs + swz(off));
                b[2 * p][0] = t[0]; b[2 * p][1] = t[2];
                b[2 * p + 1][0] = t[1]; b[2 * p + 1][1] = t[3];
            }
#pragma unroll
            for (int mt = 0; mt < 4; mt++)
#pragma unroll
                for (int nt = 0; nt < 4; nt++)
                    MMA16816(c[mt][nt], a[mt], b[nt]);
        }
        __syncthreads();
    }

    if (EPI == 0) {
        // plain fp32 epilogue: out = acc + bias
#pragma unroll
        for (int mt = 0; mt < 4; mt++) {
            int row = m0 + wm + mt * 16 + (lane >> 2);
#pragma unroll
            for (int nt = 0; nt < 4; nt++) {
                int col = n0 + wn + nt * 8 + 2 * (lane & 3);
                float2 bv = *(const float2*)(bias + col);
                float2 v0 = make_float2(c[mt][nt][0] + bv.x, c[mt][nt][1] + bv.y);
                float2 v1 = make_float2(c[mt][nt][2] + bv.x, c[mt][nt][3] + bv.y);
                *(float2*)(Cout + (size_t)row * Nd + col) = v0;
                *(float2*)(Cout + (size_t)(row + 8) * Nd + col) = v1;
            }
        }
    } else {
        // fused epilogue: relu, fp16 store, per-block exact scores2
        asm volatile("cp.async.wait_group 0;" ::: "memory");
        __syncthreads();
        float* ssm = (float*)smem;          // 128 column accumulators
        if (tid < 128) ssm[tid] = 0.0f;
        __syncthreads();

        float sacc[8];
#pragma unroll
        for (int q = 0; q < 8; q++) sacc[q] = 0.0f;

#pragma unroll
        for (int mt = 0; mt < 4; mt++) {
            int r0 = wm + mt * 16 + (lane >> 2);   // local row = n within batch
            int r1 = r0 + 8;
            float w0 = ws2[r0], w1 = ws2[r1];
#pragma unroll
            for (int nt = 0; nt < 4; nt++) {
                int col = wn + nt * 8 + 2 * (lane & 3);
                float2 bv = *(const float2*)(bias + n0 + col);
                float v0x = fmaxf(c[mt][nt][0] + bv.x, 0.0f);
                float v0y = fmaxf(c[mt][nt][1] + bv.y, 0.0f);
                float v1x = fmaxf(c[mt][nt][2] + bv.x, 0.0f);
                float v1y = fmaxf(c[mt][nt][3] + bv.y, 0.0f);
                *(__half2*)(Hout + (size_t)(m0 + r0) * Nd + n0 + col) = __floats2half2_rn(v0x, v0y);
                *(__half2*)(Hout + (size_t)(m0 + r1) * Nd + n0 + col) = __floats2half2_rn(v1x, v1y);
                sacc[nt * 2 + 0] += w0 * v0x + w1 * v1x;
                sacc[nt * 2 + 1] += w0 * v0y + w1 * v1y;
            }
        }
#pragma unroll
        for (int nt = 0; nt < 4; nt++) {
            int col = wn + nt * 8 + 2 * (lane & 3);
            atomicAdd(&ssm[col], sacc[nt * 2 + 0]);
            atomicAdd(&ssm[col + 1], sacc[nt * 2 + 1]);
        }
        __syncthreads();
        if (tid < 128)
            scores_out[(size_t)blockIdx.y * Nd + n0 + tid] = ssm[tid] + bs2[0];
    }
}

// =================== scores1: s[b,c] = sum_n x[b,n,c]*ws[n] + bs ============
__global__ void scores_kernel(const float* __restrict__ x, const float* __restrict__ ws,
                              const float* __restrict__ bs, float* __restrict__ out, int C) {
    __shared__ float w[N_];
    int tid = threadIdx.x;
    if (tid < N_) w[tid] = ws[tid];
    __syncthreads();
    int c = blockIdx.x * blockDim.x + tid;
    int b = blockIdx.y;
    const float* xp = x + (size_t)b * N_ * C + c;
    float s = 0.0f;
#pragma unroll 8
    for (int n = 0; n < N_; n++) s += xp[(size_t)n * C] * w[n];
    out[(size_t)b * C + c] = s + bs[0];
}

// =================== top-k (jax.lax.top_k tie semantics) ====================
template <int C, int KKEEP, int KPAD>
__global__ __launch_bounds__(1024) void topk_kernel(const float* __restrict__ scores,
                                                    int* __restrict__ idx_out) {
    constexpr int E = C / 1024;
    __shared__ float ss[C];
    __shared__ int   si[C];
    __shared__ int   sc[1024];
    int b = blockIdx.x, tid = threadIdx.x;
    for (int e = 0; e < E; e++) { int i = tid + e * 1024; ss[i] = scores[(size_t)b * C + i]; si[i] = i; }
    __syncthreads();
    for (int k = 2; k <= C; k <<= 1)
        for (int j = k >> 1; j > 0; j >>= 1) {
            for (int e = 0; e < E; e++) {
                int i = tid + e * 1024, ixj = i ^ j;
                if (ixj > i) {
                    float s_i = ss[i], s_x = ss[ixj];
                    int   i_i = si[i], i_x = si[ixj];
                    bool bx = (s_x > s_i) || (s_x == s_i && i_x < i_i);
                    bool dosw = ((i & k) == 0) ? bx : !bx;
                    if (dosw) { ss[i] = s_x; ss[ixj] = s_i; si[i] = i_x; si[ixj] = i_i; }
                }
            }
            __syncthreads();
        }
    int* flag = (int*)ss;
    for (int e = 0; e < E; e++) flag[tid + e * 1024] = 0;
    __syncthreads();
    for (int e = 0; e < E; e++) { int p = tid + e * 1024; if (p < KKEEP) flag[si[p]] = 1; }
    __syncthreads();
    int cnt = 0;
#pragma unroll
    for (int e = 0; e < E; e++) cnt += flag[tid * E + e];
    sc[tid] = cnt;
    __syncthreads();
    for (int off = 1; off < 1024; off <<= 1) {
        int t = (tid >= off) ? sc[tid - off] : 0;
        __syncthreads();
        sc[tid] += t;
        __syncthreads();
    }
    int base = sc[tid] - cnt;
    for (int e = 0; e < E; e++) { int c = tid * E + e; if (flag[c]) idx_out[(size_t)b * KPAD + (base++)] = c; }
}

// ======= gather1: fp32 -> fp16 [hi | lo] sections ===========================
__global__ void gather1_kernel(const float* __restrict__ src, const int* __restrict__ idx,
                               __half* __restrict__ dst, int C, int KKEEP, int KP) {
    int k = blockIdx.x * blockDim.x + threadIdx.x;
    int bn = blockIdx.y;
    int b = bn >> 7;
    if (k >= KP) return;
    float v = 0.0f;
    if (k < KKEEP) v = src[(size_t)bn * C + idx[(size_t)b * KP + k]];
    __half hi = __float2half_rn(v);
    __half lo = __float2half_rn(v - __half2float(hi));
    size_t base = (size_t)bn * (2 * (size_t)KP);
    dst[base + k] = hi;
    dst[base + KP + k] = lo;
}

// ======= gather2: fp16 h (hi plane) -> h2 hi-only ===========================
__global__ void gather2_kernel(const __half* __restrict__ src, const int* __restrict__ idx,
                               __half* __restrict__ dst, int C, int KKEEP, int KP) {
    int k = blockIdx.x * blockDim.x + threadIdx.x;
    int bn = blockIdx.y;
    int b = bn >> 7;
    if (k >= KP) return;
    __half v = __float2half_rn(0.0f);
    if (k < KKEEP) v = src[(size_t)bn * C + idx[(size_t)b * KP + k]];
    dst[(size_t)bn * KP + k] = v;
}

// ======= weight pack fp32 -> fp16 [hi | lo] =================================
__global__ void pack_split_kernel(const float* __restrict__ W, __half* __restrict__ Wp,
                                  int K, int KP) {
    int k = blockIdx.x * blockDim.x + threadIdx.x;
    int r = blockIdx.y;
    if (k >= KP) return;
    float v = (k < K) ? W[(size_t)r * K + k] : 0.0f;
    __half hi = __float2half_rn(v);
    __half lo = __float2half_rn(v - __half2float(hi));
    size_t base = (size_t)r * (2 * (size_t)KP);
    Wp[base + k] = hi;
    Wp[base + KP + k] = lo;
}

// =================== host side ==============================================
extern "C" void kernel_launch(void* const* d_in, const int* in_sizes, int n_in,
                              void* d_out, int out_size) {
    const float* x   = (const float*)d_in[0];
    const float* ws1 = (const float*)d_in[1];
    const float* bs1 = (const float*)d_in[2];
    const float* W1  = (const float*)d_in[3];
    const float* b1  = (const float*)d_in[4];
    const float* ws2 = (const float*)d_in[5];
    const float* bs2 = (const float*)d_in[6];
    const float* W2  = (const float*)d_in[7];
    const float* b2  = (const float*)d_in[8];
    float* out = (float*)d_out;

    float *scores1, *scores2;
    __half *x1, *h, *h2, *W1p, *W2p;
    int *idx1, *idx2;
    cudaGetSymbolAddress((void**)&scores1, g_scores1);
    cudaGetSymbolAddress((void**)&idx1,    g_idx1);
    cudaGetSymbolAddress((void**)&x1,      g_x1);
    cudaGetSymbolAddress((void**)&h,       g_h);
    cudaGetSymbolAddress((void**)&scores2, g_scores2);
    cudaGetSymbolAddress((void**)&idx2,    g_idx2);
    cudaGetSymbolAddress((void**)&h2,      g_h2);
    cudaGetSymbolAddress((void**)&W1p,     g_W1p);
    cudaGetSymbolAddress((void**)&W2p,     g_W2p);

    cudaFuncSetAttribute(gemm_hmma<0>, cudaFuncAttributeMaxDynamicSharedMemorySize, GEMM_SMEM);
    cudaFuncSetAttribute(gemm_hmma<1>, cudaFuncAttributeMaxDynamicSharedMemorySize, GEMM_SMEM);

    // weight packs ([hi|lo] fp16)
    pack_split_kernel<<<dim3((K1P + 255) / 256, H_), 256>>>(W1, W1p, K1_, K1P);
    pack_split_kernel<<<dim3((K2P + 255) / 256, D_), 256>>>(W2, W2p, K2_, K2P);

    // stage 1: prune x (D -> K1)
    scores_kernel<<<dim3(D_ / 256, B_), 256>>>(x, ws1, bs1, scores1, D_);
    topk_kernel<D_, K1_, K1P><<<B_, 1024>>>(scores1, idx1);
    gather1_kernel<<<dim3((K1P + 255) / 256, B_ * N_), 256>>>(x, idx1, x1, D_, K1_, K1P);

    // net1 (3-term fp16) + fused relu/scores2/half-store
    gemm_hmma<1><<<dim3(H_ / 128, (B_ * N_) / 128), 256, GEMM_SMEM>>>(
        x1, W1p, b1, nullptr, h, scores2, ws2, bs2,
        H_, KCH1, NCK1, 1, 2 * K1P, 2 * K1P);

    // stage 2: prune h (H -> K2)
    topk_kernel<H_, K2_, K2P><<<B_, 1024>>>(scores2, idx2);
    gather2_kernel<<<dim3((K2P + 255) / 256, B_ * N_), 256>>>(h, idx2, h2, H_, K2_, K2P);

    // net2 (2-term fp16): out = h2 @ W2^T + b2
    gemm_hmma<0><<<dim3(D_ / 128, (B_ * N_) / 128), 256, GEMM_SMEM>>>(
        h2, W2p, b2, out, nullptr, nullptr, nullptr, nullptr,
        D_, KCH2, NCK2, 2, K2P, 2 * K2P);
}

// round 8
// speedup vs baseline: 2.9575x; 1.3197x over previous
#include <cuda_runtime.h>
#include <cuda_fp16.h>
#include <cstdint>

// Problem dims
#define B_  256
#define N_  128
#define D_  1024
#define H_  4096
#define K1_ 819
#define K2_ 3276
#define K1P 832                 // padded keep-counts (multiple of 64)
#define K2P 3328
#define NCK1 (K1P/64)           // 13 chunk-cols per section
#define NCK2 (K2P/64)           // 52
#define KCH1 (3*NCK1)           // 39 total K-chunks (3-term GEMM1)
#define KCH2 NCK2               // 52 (1-term GEMM2)

// ---------------- scratch (device globals; no allocation allowed) ----------
__device__ __align__(256) float  g_scores1[B_ * D_];
__device__ __align__(256) int    g_idx1[B_ * K1P];
__device__ __align__(256) __half g_x1[(size_t)B_ * N_ * 2 * K1P];  // [hi|lo]
__device__ __align__(256) __half g_h[(size_t)B_ * N_ * H_];        // hi plane
__device__ __align__(256) float  g_scores2[B_ * H_];
__device__ __align__(256) int    g_idx2[B_ * K2P];
__device__ __align__(256) __half g_h2[(size_t)B_ * N_ * K2P];      // hi only
__device__ __align__(256) __half g_W1p[(size_t)H_ * 2 * K1P];      // [hi|lo]
__device__ __align__(256) __half g_W2p[(size_t)D_ * K2P];          // hi only

// =================== helpers ================================================
__device__ __forceinline__ uint32_t smem_u32(const void* p) {
    uint32_t a;
    asm("{ .reg .u64 t; cvta.to.shared.u64 t, %1; cvt.u32.u64 %0, t; }" : "=r"(a) : "l"(p));
    return a;
}
__device__ __forceinline__ void cp16(uint32_t dst, const void* src) {
    asm volatile("cp.async.cg.shared.global [%0], [%1], 16;" :: "r"(dst), "l"(src) : "memory");
}
__device__ __forceinline__ uint32_t swz(uint32_t off) { return off ^ ((off >> 3) & 0x70); }

#define LDSM_X4(r, addr) \
    asm volatile("ldmatrix.sync.aligned.m8n8.x4.shared.b16 {%0,%1,%2,%3}, [%4];" \
        : "=r"((r)[0]), "=r"((r)[1]), "=r"((r)[2]), "=r"((r)[3]) : "r"(addr))

#define MMA16816(c, a, b) \
    asm volatile("mma.sync.aligned.m16n8k16.row.col.f32.f16.f16.f32 " \
        "{%0,%1,%2,%3}, {%4,%5,%6,%7}, {%8,%9}, {%0,%1,%2,%3};" \
        : "+f"((c)[0]), "+f"((c)[1]), "+f"((c)[2]), "+f"((c)[3]) \
        : "r"((a)[0]), "r"((a)[1]), "r"((a)[2]), "r"((a)[3]), "r"((b)[0]), "r"((b)[1]))

// =================== fp16 HMMA GEMM, 128(M)x256(N)x64 tiles ================
// 8 warps in 2(M)x4(N) grid, warp tile 64x64. 4-stage cp.async pipeline.
// mode 1 (3-term): t=k/ncol: (t0) hiA*hiB (t1) hiA*loB (t2) loA*hiB
// mode 0 (1-term): direct k.
// EPI 0: Cout = acc + bias (fp32)
// EPI 1: v=relu(acc+bias); Hout=half(v); scores_out[b][col]=sum_n ws2[n]*v+bs2
#define STAGES 4
#define STAGE_BYTES 49152       // (128+256) rows x 128B
#define ATILE 16384
#define GEMM_SMEM (STAGES * STAGE_BYTES)   // 192 KB

template <int EPI>
__global__ __launch_bounds__(256, 1) void gemm_hmma(
    const __half* __restrict__ A, const __half* __restrict__ Bw,
    const float* __restrict__ bias, float* __restrict__ Cout,
    __half* __restrict__ Hout, float* __restrict__ scores_out,
    const float* __restrict__ ws2, const float* __restrict__ bs2,
    int Nd, int kchunks, int ncol, int mode, int kstA, int kstB)
{
    extern __shared__ char smem[];
    const uint32_t sbase = smem_u32(smem);
    const int tid = threadIdx.x, wid = tid >> 5, lane = tid & 31;
    const int m0 = blockIdx.y * 128, n0 = blockIdx.x * 256;
    const int wm = (wid >> 2) * 64, wn = (wid & 3) * 64;

    float c[4][8][4];
#pragma unroll
    for (int i = 0; i < 4; i++)
#pragma unroll
        for (int j = 0; j < 8; j++)
#pragma unroll
            for (int q = 0; q < 4; q++) c[i][j][q] = 0.0f;

    const int lr = tid >> 3;            // 0..31
    const int lcb = (tid & 7) * 16;     // 0..112

#define LOAD_CHUNK(k) do { \
    int _ka, _kb; \
    if (mode == 1) { \
        int _t = (k) / ncol, _kk = (k) - _t * ncol; \
        _ka = (_t == 2) ? ncol + _kk : _kk; \
        _kb = (_t == 1) ? ncol + _kk : _kk; \
    } else { _ka = (k); _kb = (k); } \
    int _s = (k) & (STAGES - 1); \
    uint32_t _as = sbase + _s * STAGE_BYTES; \
    uint32_t _bs = _as + ATILE; \
    const char* _Ag = (const char*)A + (size_t)_ka * 128 + lcb + (size_t)(m0 + lr) * (size_t)kstA * 2; \
    const char* _Bg = (const char*)Bw + (size_t)_kb * 128 + lcb + (size_t)(n0 + lr) * (size_t)kstB * 2; \
    uint32_t _d = swz((uint32_t)(lr * 128 + lcb)); \
    size_t _ra = (size_t)kstA * 64, _rb = (size_t)kstB * 64; \
    _Pragma("unroll") \
    for (int _w = 0; _w < 4; _w++) cp16(_as + _d + _w * 0x1000, _Ag + _w * _ra); \
    _Pragma("unroll") \
    for (int _w = 0; _w < 8; _w++) cp16(_bs + _d + _w * 0x1000, _Bg + _w * _rb); \
} while (0)

    for (int k = 0; k < STAGES - 1 && k < kchunks; k++) {
        LOAD_CHUNK(k);
        asm volatile("cp.async.commit_group;" ::: "memory");
    }

    for (int k = 0; k < kchunks; k++) {
        asm volatile("cp.async.wait_group %0;" :: "n"(STAGES - 2) : "memory");
        __syncthreads();

        if (k + STAGES - 1 < kchunks) LOAD_CHUNK(k + STAGES - 1);
        asm volatile("cp.async.commit_group;" ::: "memory");

        const int st = k & (STAGES - 1);
        const uint32_t as = sbase + st * STAGE_BYTES;
        const uint32_t bs = as + ATILE;
#pragma unroll
        for (int ks = 0; ks < 4; ks++) {
            uint32_t a[4][4], b[8][2];
            const int cb = ks * 32 + ((lane >> 4) << 4);
#pragma unroll
            for (int mt = 0; mt < 4; mt++) {
                uint32_t off = (uint32_t)((wm + mt * 16 + (lane & 15)) * 128 + cb);
                LDSM_X4(a[mt], as + swz(off));
            }
#pragma unroll
            for (int p = 0; p < 4; p++) {
                uint32_t t[4];
                uint32_t off = (uint32_t)((wn + p * 16 + (lane & 15)) * 128 + cb);
                LDSM_X4(t, bs + swz(off));
                b[2 * p][0] = t[0]; b[2 * p][1] = t[2];
                b[2 * p + 1][0] = t[1]; b[2 * p + 1][1] = t[3];
            }
#pragma unroll
            for (int mt = 0; mt < 4; mt++)
#pragma unroll
                for (int nt = 0; nt < 8; nt++)
                    MMA16816(c[mt][nt], a[mt], b[nt]);
        }
        __syncthreads();
    }

    if (EPI == 0) {
#pragma unroll
        for (int mt = 0; mt < 4; mt++) {
            int row = m0 + wm + mt * 16 + (lane >> 2);
#pragma unroll
            for (int nt = 0; nt < 8; nt++) {
                int col = n0 + wn + nt * 8 + 2 * (lane & 3);
                float2 bv = *(const float2*)(bias + col);
                float2 v0 = make_float2(c[mt][nt][0] + bv.x, c[mt][nt][1] + bv.y);
                float2 v1 = make_float2(c[mt][nt][2] + bv.x, c[mt][nt][3] + bv.y);
                *(float2*)(Cout + (size_t)row * Nd + col) = v0;
                *(float2*)(Cout + (size_t)(row + 8) * Nd + col) = v1;
            }
        }
    } else {
        // fused epilogue: relu, fp16 store, exact per-block scores2
        asm volatile("cp.async.wait_group 0;" ::: "memory");
        __syncthreads();
        float* ssm = (float*)smem;          // 256 column accumulators
        ssm[tid] = 0.0f;
        __syncthreads();

        float sacc[16];
#pragma unroll
        for (int q = 0; q < 16; q++) sacc[q] = 0.0f;

#pragma unroll
        for (int mt = 0; mt < 4; mt++) {
            int r0 = wm + mt * 16 + (lane >> 2);   // local row = n within batch
            int r1 = r0 + 8;
            float w0 = ws2[r0], w1 = ws2[r1];
#pragma unroll
            for (int nt = 0; nt < 8; nt++) {
                int col = wn + nt * 8 + 2 * (lane & 3);
                float2 bv = *(const float2*)(bias + n0 + col);
                float v0x = fmaxf(c[mt][nt][0] + bv.x, 0.0f);
                float v0y = fmaxf(c[mt][nt][1] + bv.y, 0.0f);
                float v1x = fmaxf(c[mt][nt][2] + bv.x, 0.0f);
                float v1y = fmaxf(c[mt][nt][3] + bv.y, 0.0f);
                *(__half2*)(Hout + (size_t)(m0 + r0) * Nd + n0 + col) = __floats2half2_rn(v0x, v0y);
                *(__half2*)(Hout + (size_t)(m0 + r1) * Nd + n0 + col) = __floats2half2_rn(v1x, v1y);
                sacc[nt * 2 + 0] += w0 * v0x + w1 * v1x;
                sacc[nt * 2 + 1] += w0 * v0y + w1 * v1y;
            }
        }
#pragma unroll
        for (int nt = 0; nt < 8; nt++) {
            int col = wn + nt * 8 + 2 * (lane & 3);
            atomicAdd(&ssm[col], sacc[nt * 2 + 0]);
            atomicAdd(&ssm[col + 1], sacc[nt * 2 + 1]);
        }
        __syncthreads();
        scores_out[(size_t)blockIdx.y * Nd + n0 + tid] = ssm[tid] + bs2[0];
    }
}

// =================== scores1: s[b,c] = sum_n x[b,n,c]*ws[n] + bs ============
__global__ void scores_kernel(const float* __restrict__ x, const float* __restrict__ ws,
                              const float* __restrict__ bs, float* __restrict__ out, int C) {
    __shared__ float w[N_];
    int tid = threadIdx.x;
    if (tid < N_) w[tid] = ws[tid];
    __syncthreads();
    int c = blockIdx.x * blockDim.x + tid;
    int b = blockIdx.y;
    const float* xp = x + (size_t)b * N_ * C + c;
    float s = 0.0f;
#pragma unroll 8
    for (int n = 0; n < N_; n++) s += xp[(size_t)n * C] * w[n];
    out[(size_t)b * C + c] = s + bs[0];
}

// =================== top-k (jax.lax.top_k tie semantics) ====================
template <int C, int KKEEP, int KPAD>
__global__ __launch_bounds__(1024) void topk_kernel(const float* __restrict__ scores,
                                                    int* __restrict__ idx_out) {
    constexpr int E = C / 1024;
    __shared__ float ss[C];
    __shared__ int   si[C];
    __shared__ int   sc[1024];
    int b = blockIdx.x, tid = threadIdx.x;
    for (int e = 0; e < E; e++) { int i = tid + e * 1024; ss[i] = scores[(size_t)b * C + i]; si[i] = i; }
    __syncthreads();
    for (int k = 2; k <= C; k <<= 1)
        for (int j = k >> 1; j > 0; j >>= 1) {
            for (int e = 0; e < E; e++) {
                int i = tid + e * 1024, ixj = i ^ j;
                if (ixj > i) {
                    float s_i = ss[i], s_x = ss[ixj];
                    int   i_i = si[i], i_x = si[ixj];
                    bool bx = (s_x > s_i) || (s_x == s_i && i_x < i_i);
                    bool dosw = ((i & k) == 0) ? bx : !bx;
                    if (dosw) { ss[i] = s_x; ss[ixj] = s_i; si[i] = i_x; si[ixj] = i_i; }
                }
            }
            __syncthreads();
        }
    int* flag = (int*)ss;
    for (int e = 0; e < E; e++) flag[tid + e * 1024] = 0;
    __syncthreads();
    for (int e = 0; e < E; e++) { int p = tid + e * 1024; if (p < KKEEP) flag[si[p]] = 1; }
    __syncthreads();
    int cnt = 0;
#pragma unroll
    for (int e = 0; e < E; e++) cnt += flag[tid * E + e];
    sc[tid] = cnt;
    __syncthreads();
    for (int off = 1; off < 1024; off <<= 1) {
        int t = (tid >= off) ? sc[tid - off] : 0;
        __syncthreads();
        sc[tid] += t;
        __syncthreads();
    }
    int base = sc[tid] - cnt;
    for (int e = 0; e < E; e++) { int c = tid * E + e; if (flag[c]) idx_out[(size_t)b * KPAD + (base++)] = c; }
}

// ======= gather1: fp32 -> fp16 [hi | lo] sections ===========================
__global__ void gather1_kernel(const float* __restrict__ src, const int* __restrict__ idx,
                               __half* __restrict__ dst, int C, int KKEEP, int KP) {
    int k = blockIdx.x * blockDim.x + threadIdx.x;
    int bn = blockIdx.y;
    int b = bn >> 7;
    if (k >= KP) return;
    float v = 0.0f;
    if (k < KKEEP) v = src[(size_t)bn * C + idx[(size_t)b * KP + k]];
    __half hi = __float2half_rn(v);
    __half lo = __float2half_rn(v - __half2float(hi));
    size_t base = (size_t)bn * (2 * (size_t)KP);
    dst[base + k] = hi;
    dst[base + KP + k] = lo;
}

// ======= gather2: fp16 h (hi plane) -> h2 hi-only ===========================
__global__ void gather2_kernel(const __half* __restrict__ src, const int* __restrict__ idx,
                               __half* __restrict__ dst, int C, int KKEEP, int KP) {
    int k = blockIdx.x * blockDim.x + threadIdx.x;
    int bn = blockIdx.y;
    int b = bn >> 7;
    if (k >= KP) return;
    __half v = __float2half_rn(0.0f);
    if (k < KKEEP) v = src[(size_t)bn * C + idx[(size_t)b * KP + k]];
    dst[(size_t)bn * KP + k] = v;
}

// ======= weight packs ========================================================
__global__ void pack_split_kernel(const float* __restrict__ W, __half* __restrict__ Wp,
                                  int K, int KP) {
    int k = blockIdx.x * blockDim.x + threadIdx.x;
    int r = blockIdx.y;
    if (k >= KP) return;
    float v = (k < K) ? W[(size_t)r * K + k] : 0.0f;
    __half hi = __float2half_rn(v);
    __half lo = __float2half_rn(v - __half2float(hi));
    size_t base = (size_t)r * (2 * (size_t)KP);
    Wp[base + k] = hi;
    Wp[base + KP + k] = lo;
}
__global__ void pack_hi_kernel(const float* __restrict__ W, __half* __restrict__ Wp,
                               int K, int KP) {
    int k = blockIdx.x * blockDim.x + threadIdx.x;
    int r = blockIdx.y;
    if (k >= KP) return;
    float v = (k < K) ? W[(size_t)r * K + k] : 0.0f;
    Wp[(size_t)r * KP + k] = __float2half_rn(v);
}

// =================== host side ==============================================
extern "C" void kernel_launch(void* const* d_in, const int* in_sizes, int n_in,
                              void* d_out, int out_size) {
    const float* x   = (const float*)d_in[0];
    const float* ws1 = (const float*)d_in[1];
    const float* bs1 = (const float*)d_in[2];
    const float* W1  = (const float*)d_in[3];
    const float* b1  = (const float*)d_in[4];
    const float* ws2 = (const float*)d_in[5];
    const float* bs2 = (const float*)d_in[6];
    const float* W2  = (const float*)d_in[7];
    const float* b2  = (const float*)d_in[8];
    float* out = (float*)d_out;

    float *scores1, *scores2;
    __half *x1, *h, *h2, *W1p, *W2p;
    int *idx1, *idx2;
    cudaGetSymbolAddress((void**)&scores1, g_scores1);
    cudaGetSymbolAddress((void**)&idx1,    g_idx1);
    cudaGetSymbolAddress((void**)&x1,      g_x1);
    cudaGetSymbolAddress((void**)&h,       g_h);
    cudaGetSymbolAddress((void**)&scores2, g_scores2);
    cudaGetSymbolAddress((void**)&idx2,    g_idx2);
    cudaGetSymbolAddress((void**)&h2,      g_h2);
    cudaGetSymbolAddress((void**)&W1p,     g_W1p);
    cudaGetSymbolAddress((void**)&W2p,     g_W2p);

    cudaFuncSetAttribute(gemm_hmma<0>, cudaFuncAttributeMaxDynamicSharedMemorySize, GEMM_SMEM);
    cudaFuncSetAttribute(gemm_hmma<1>, cudaFuncAttributeMaxDynamicSharedMemorySize, GEMM_SMEM);

    // weight packs
    pack_split_kernel<<<dim3((K1P + 255) / 256, H_), 256>>>(W1, W1p, K1_, K1P);
    pack_hi_kernel<<<dim3((K2P + 255) / 256, D_), 256>>>(W2, W2p, K2_, K2P);

    // stage 1: prune x (D -> K1)
    scores_kernel<<<dim3(D_ / 256, B_), 256>>>(x, ws1, bs1, scores1, D_);
    topk_kernel<D_, K1_, K1P><<<B_, 1024>>>(scores1, idx1);
    gather1_kernel<<<dim3((K1P + 255) / 256, B_ * N_), 256>>>(x, idx1, x1, D_, K1_, K1P);

    // net1 (3-term fp16) + fused relu/scores2/half-store
    gemm_hmma<1><<<dim3(H_ / 256, (B_ * N_) / 128), 256, GEMM_SMEM>>>(
        x1, W1p, b1, nullptr, h, scores2, ws2, bs2,
        H_, KCH1, NCK1, 1, 2 * K1P, 2 * K1P);

    // stage 2: prune h (H -> K2)
    topk_kernel<H_, K2_, K2P><<<B_, 1024>>>(scores2, idx2);
    gather2_kernel<<<dim3((K2P + 255) / 256, B_ * N_), 256>>>(h, idx2, h2, H_, K2_, K2P);

    // net2 (1-term fp16): out = h2 @ W2^T + b2
    gemm_hmma<0><<<dim3(D_ / 256, (B_ * N_) / 128), 256, GEMM_SMEM>>>(
        h2, W2p, b2, out, nullptr, nullptr, nullptr, nullptr,
        D_, KCH2, NCK2, 0, K2P, K2P);
}

// round 9
// speedup vs baseline: 2.9788x; 1.0072x over previous
#include <cuda_runtime.h>
#include <cuda_fp16.h>
#include <cstdint>

// Problem dims
#define B_  256
#define N_  128
#define D_  1024
#define H_  4096
#define K1_ 819
#define K2_ 3276
#define K1P 832                 // padded keep-counts (multiple of 64)
#define K2P 3328
#define NCK1 (K1P/64)           // 13 chunk-cols per section
#define NCK2 (K2P/64)           // 52
#define KCH1 (3*NCK1)           // 39 total K-chunks (3-term GEMM1)
#define KCH2 NCK2               // 52 (1-term GEMM2)

// ---------------- scratch (device globals; no allocation allowed) ----------
__device__ __align__(256) float  g_scores1[B_ * D_];
__device__ __align__(256) int    g_idx1[B_ * K1P];
__device__ __align__(256) __half g_x1[(size_t)B_ * N_ * 2 * K1P];  // [hi|lo]
__device__ __align__(256) __half g_h[(size_t)B_ * N_ * H_];        // hi plane
__device__ __align__(256) float  g_scores2[B_ * H_];
__device__ __align__(256) int    g_idx2[B_ * K2P];
__device__ __align__(256) __half g_h2[(size_t)B_ * N_ * K2P];      // hi only
__device__ __align__(256) __half g_W1p[(size_t)H_ * 2 * K1P];      // [hi|lo]
__device__ __align__(256) __half g_W2p[(size_t)D_ * K2P];          // hi only

// =================== helpers ================================================
__device__ __forceinline__ uint32_t smem_u32(const void* p) {
    uint32_t a;
    asm("{ .reg .u64 t; cvta.to.shared.u64 t, %1; cvt.u32.u64 %0, t; }" : "=r"(a) : "l"(p));
    return a;
}
__device__ __forceinline__ void cp16(uint32_t dst, const void* src) {
    asm volatile("cp.async.cg.shared.global [%0], [%1], 16;" :: "r"(dst), "l"(src) : "memory");
}
__device__ __forceinline__ uint32_t swz(uint32_t off) { return off ^ ((off >> 3) & 0x70); }

#define LDSM_X4(r, addr) \
    asm volatile("ldmatrix.sync.aligned.m8n8.x4.shared.b16 {%0,%1,%2,%3}, [%4];" \
        : "=r"((r)[0]), "=r"((r)[1]), "=r"((r)[2]), "=r"((r)[3]) : "r"(addr))

#define MMA16816(c, a, b) \
    asm volatile("mma.sync.aligned.m16n8k16.row.col.f32.f16.f16.f32 " \
        "{%0,%1,%2,%3}, {%4,%5,%6,%7}, {%8,%9}, {%0,%1,%2,%3};" \
        : "+f"((c)[0]), "+f"((c)[1]), "+f"((c)[2]), "+f"((c)[3]) \
        : "r"((a)[0]), "r"((a)[1]), "r"((a)[2]), "r"((a)[3]), "r"((b)[0]), "r"((b)[1]))

// =================== fp16 HMMA GEMM, 128(M)x256(N)x64 tiles ================
// 8 warps in 2(M)x4(N) grid, warp tile 64x64. 4-stage cp.async pipeline,
// register double-buffered ldmatrix fragments.
// mode 1 (3-term): t=k/ncol: (t0) hiA*hiB (t1) hiA*loB (t2) loA*hiB
// mode 0 (1-term): direct k.
// EPI 0: Cout = acc + bias (fp32)
// EPI 1: v=relu(acc+bias); Hout=half(v); scores_out[b][col]=sum_n ws2[n]*v+bs2
#define STAGES 4
#define STAGE_BYTES 49152       // (128+256) rows x 128B
#define ATILE 16384
#define GEMM_SMEM (STAGES * STAGE_BYTES)   // 192 KB

template <int EPI>
__global__ __launch_bounds__(256, 1) void gemm_hmma(
    const __half* __restrict__ A, const __half* __restrict__ Bw,
    const float* __restrict__ bias, float* __restrict__ Cout,
    __half* __restrict__ Hout, float* __restrict__ scores_out,
    const float* __restrict__ ws2, const float* __restrict__ bs2,
    int Nd, int kchunks, int ncol, int mode, int kstA, int kstB)
{
    extern __shared__ char smem[];
    const uint32_t sbase = smem_u32(smem);
    const int tid = threadIdx.x, wid = tid >> 5, lane = tid & 31;
    const int m0 = blockIdx.y * 128, n0 = blockIdx.x * 256;
    const int wm = (wid >> 2) * 64, wn = (wid & 3) * 64;

    float c[4][8][4];
#pragma unroll
    for (int i = 0; i < 4; i++)
#pragma unroll
        for (int j = 0; j < 8; j++)
#pragma unroll
            for (int q = 0; q < 4; q++) c[i][j][q] = 0.0f;

    const int lr = tid >> 3;            // 0..31
    const int lcb = (tid & 7) * 16;     // 0..112
    // ldsm row base addresses (per-thread, fixed across chunks)
    const int arow = wm + (lane & 15);
    const int brow = wn + (lane & 15);
    const int csel = (lane >> 4) << 4;  // 0 or 16

#define LOAD_CHUNK(k) do { \
    int _ka, _kb; \
    if (mode == 1) { \
        int _t = (k) / ncol, _kk = (k) - _t * ncol; \
        _ka = (_t == 2) ? ncol + _kk : _kk; \
        _kb = (_t == 1) ? ncol + _kk : _kk; \
    } else { _ka = (k); _kb = (k); } \
    int _s = (k) & (STAGES - 1); \
    uint32_t _as = sbase + _s * STAGE_BYTES; \
    uint32_t _bs = _as + ATILE; \
    const char* _Ag = (const char*)A + (size_t)_ka * 128 + lcb + (size_t)(m0 + lr) * (size_t)kstA * 2; \
    const char* _Bg = (const char*)Bw + (size_t)_kb * 128 + lcb + (size_t)(n0 + lr) * (size_t)kstB * 2; \
    uint32_t _d = swz((uint32_t)(lr * 128 + lcb)); \
    size_t _ra = (size_t)kstA * 64, _rb = (size_t)kstB * 64; \
    _Pragma("unroll") \
    for (int _w = 0; _w < 4; _w++) cp16(_as + _d + _w * 0x1000, _Ag + _w * _ra); \
    _Pragma("unroll") \
    for (int _w = 0; _w < 8; _w++) cp16(_bs + _d + _w * 0x1000, _Bg + _w * _rb); \
} while (0)

// load one k-step's register fragments from stage (as, bs)
#define LOAD_FRAGS(ks, a, b) do { \
    const int _cb = (ks) * 32 + csel; \
    _Pragma("unroll") \
    for (int _mt = 0; _mt < 4; _mt++) { \
        uint32_t _off = (uint32_t)((arow + _mt * 16) * 128 + _cb); \
        LDSM_X4((a)[_mt], as + swz(_off)); \
    } \
    _Pragma("unroll") \
    for (int _p = 0; _p < 4; _p++) { \
        uint32_t _t4[4]; \
        uint32_t _off = (uint32_t)((brow + _p * 16) * 128 + _cb); \
        LDSM_X4(_t4, bs + swz(_off)); \
        (b)[2 * _p][0] = _t4[0]; (b)[2 * _p][1] = _t4[2]; \
        (b)[2 * _p + 1][0] = _t4[1]; (b)[2 * _p + 1][1] = _t4[3]; \
    } \
} while (0)

#define DO_MMAS(a, b) do { \
    _Pragma("unroll") \
    for (int _mt = 0; _mt < 4; _mt++) \
        _Pragma("unroll") \
        for (int _nt = 0; _nt < 8; _nt++) \
            MMA16816(c[_mt][_nt], (a)[_mt], (b)[_nt]); \
} while (0)

    for (int k = 0; k < STAGES - 1 && k < kchunks; k++) {
        LOAD_CHUNK(k);
        asm volatile("cp.async.commit_group;" ::: "memory");
    }

    for (int k = 0; k < kchunks; k++) {
        asm volatile("cp.async.wait_group %0;" :: "n"(STAGES - 2) : "memory");
        __syncthreads();

        const int st = k & (STAGES - 1);
        const uint32_t as = sbase + st * STAGE_BYTES;
        const uint32_t bs = as + ATILE;

        // register double-buffered k-steps
        uint32_t a0[4][4], b0[8][2], a1[4][4], b1[8][2];
        LOAD_FRAGS(0, a0, b0);

        if (k + STAGES - 1 < kchunks) LOAD_CHUNK(k + STAGES - 1);
        asm volatile("cp.async.commit_group;" ::: "memory");

        LOAD_FRAGS(1, a1, b1);
        DO_MMAS(a0, b0);
        LOAD_FRAGS(2, a0, b0);
        DO_MMAS(a1, b1);
        LOAD_FRAGS(3, a1, b1);
        DO_MMAS(a0, b0);
        DO_MMAS(a1, b1);
    }

    if (EPI == 0) {
#pragma unroll
        for (int mt = 0; mt < 4; mt++) {
            int row = m0 + wm + mt * 16 + (lane >> 2);
#pragma unroll
            for (int nt = 0; nt < 8; nt++) {
                int col = n0 + wn + nt * 8 + 2 * (lane & 3);
                float2 bv = *(const float2*)(bias + col);
                float2 v0 = make_float2(c[mt][nt][0] + bv.x, c[mt][nt][1] + bv.y);
                float2 v1 = make_float2(c[mt][nt][2] + bv.x, c[mt][nt][3] + bv.y);
                *(float2*)(Cout + (size_t)row * Nd + col) = v0;
                *(float2*)(Cout + (size_t)(row + 8) * Nd + col) = v1;
            }
        }
    } else {
        // fused epilogue: relu, fp16 store, exact per-block scores2
        asm volatile("cp.async.wait_group 0;" ::: "memory");
        __syncthreads();
        float* ssm = (float*)smem;          // 256 column accumulators
        ssm[tid] = 0.0f;
        __syncthreads();

        float sacc[16];
#pragma unroll
        for (int q = 0; q < 16; q++) sacc[q] = 0.0f;

#pragma unroll
        for (int mt = 0; mt < 4; mt++) {
            int r0 = wm + mt * 16 + (lane >> 2);   // local row = n within batch
            int r1 = r0 + 8;
            float w0 = ws2[r0], w1 = ws2[r1];
#pragma unroll
            for (int nt = 0; nt < 8; nt++) {
                int col = wn + nt * 8 + 2 * (lane & 3);
                float2 bv = *(const float2*)(bias + n0 + col);
                float v0x = fmaxf(c[mt][nt][0] + bv.x, 0.0f);
                float v0y = fmaxf(c[mt][nt][1] + bv.y, 0.0f);
                float v1x = fmaxf(c[mt][nt][2] + bv.x, 0.0f);
                float v1y = fmaxf(c[mt][nt][3] + bv.y, 0.0f);
                *(__half2*)(Hout + (size_t)(m0 + r0) * Nd + n0 + col) = __floats2half2_rn(v0x, v0y);
                *(__half2*)(Hout + (size_t)(m0 + r1) * Nd + n0 + col) = __floats2half2_rn(v1x, v1y);
                sacc[nt * 2 + 0] += w0 * v0x + w1 * v1x;
                sacc[nt * 2 + 1] += w0 * v0y + w1 * v1y;
            }
        }
#pragma unroll
        for (int nt = 0; nt < 8; nt++) {
            int col = wn + nt * 8 + 2 * (lane & 3);
            atomicAdd(&ssm[col], sacc[nt * 2 + 0]);
            atomicAdd(&ssm[col + 1], sacc[nt * 2 + 1]);
        }
        __syncthreads();
        scores_out[(size_t)blockIdx.y * Nd + n0 + tid] = ssm[tid] + bs2[0];
    }
}

// =================== scores1: s[b,c] = sum_n x[b,n,c]*ws[n] + bs ============
__global__ void scores_kernel(const float* __restrict__ x, const float* __restrict__ ws,
                              const float* __restrict__ bs, float* __restrict__ out, int C) {
    __shared__ float w[N_];
    int tid = threadIdx.x;
    if (tid < N_) w[tid] = ws[tid];
    __syncthreads();
    int c = blockIdx.x * blockDim.x + tid;
    int b = blockIdx.y;
    const float* xp = x + (size_t)b * N_ * C + c;
    float s = 0.0f;
#pragma unroll 8
    for (int n = 0; n < N_; n++) s += xp[(size_t)n * C] * w[n];
    out[(size_t)b * C + c] = s + bs[0];
}

// =================== top-k (jax.lax.top_k tie semantics) ====================
template <int C, int KKEEP, int KPAD>
__global__ __launch_bounds__(1024) void topk_kernel(const float* __restrict__ scores,
                                                    int* __restrict__ idx_out) {
    constexpr int E = C / 1024;
    __shared__ float ss[C];
    __shared__ int   si[C];
    __shared__ int   sc[1024];
    int b = blockIdx.x, tid = threadIdx.x;
    for (int e = 0; e < E; e++) { int i = tid + e * 1024; ss[i] = scores[(size_t)b * C + i]; si[i] = i; }
    __syncthreads();
    for (int k = 2; k <= C; k <<= 1)
        for (int j = k >> 1; j > 0; j >>= 1) {
            for (int e = 0; e < E; e++) {
                int i = tid + e * 1024, ixj = i ^ j;
                if (ixj > i) {
                    float s_i = ss[i], s_x = ss[ixj];
                    int   i_i = si[i], i_x = si[ixj];
                    bool bx = (s_x > s_i) || (s_x == s_i && i_x < i_i);
                    bool dosw = ((i & k) == 0) ? bx : !bx;
                    if (dosw) { ss[i] = s_x; ss[ixj] = s_i; si[i] = i_x; si[ixj] = i_i; }
                }
            }
            __syncthreads();
        }
    int* flag = (int*)ss;
    for (int e = 0; e < E; e++) flag[tid + e * 1024] = 0;
    __syncthreads();
    for (int e = 0; e < E; e++) { int p = tid + e * 1024; if (p < KKEEP) flag[si[p]] = 1; }
    __syncthreads();
    int cnt = 0;
#pragma unroll
    for (int e = 0; e < E; e++) cnt += flag[tid * E + e];
    sc[tid] = cnt;
    __syncthreads();
    for (int off = 1; off < 1024; off <<= 1) {
        int t = (tid >= off) ? sc[tid - off] : 0;
        __syncthreads();
        sc[tid] += t;
        __syncthreads();
    }
    int base = sc[tid] - cnt;
    for (int e = 0; e < E; e++) { int c = tid * E + e; if (flag[c]) idx_out[(size_t)b * KPAD + (base++)] = c; }
}

// ======= gather1: fp32 -> fp16 [hi | lo] sections ===========================
__global__ void gather1_kernel(const float* __restrict__ src, const int* __restrict__ idx,
                               __half* __restrict__ dst, int C, int KKEEP, int KP) {
    int k = blockIdx.x * blockDim.x + threadIdx.x;
    int bn = blockIdx.y;
    int b = bn >> 7;
    if (k >= KP) return;
    float v = 0.0f;
    if (k < KKEEP) v = src[(size_t)bn * C + idx[(size_t)b * KP + k]];
    __half hi = __float2half_rn(v);
    __half lo = __float2half_rn(v - __half2float(hi));
    size_t base = (size_t)bn * (2 * (size_t)KP);
    dst[base + k] = hi;
    dst[base + KP + k] = lo;
}

// ======= gather2: fp16 h (hi plane) -> h2 hi-only ===========================
__global__ void gather2_kernel(const __half* __restrict__ src, const int* __restrict__ idx,
                               __half* __restrict__ dst, int C, int KKEEP, int KP) {
    int k = blockIdx.x * blockDim.x + threadIdx.x;
    int bn = blockIdx.y;
    int b = bn >> 7;
    if (k >= KP) return;
    __half v = __float2half_rn(0.0f);
    if (k < KKEEP) v = src[(size_t)bn * C + idx[(size_t)b * KP + k]];
    dst[(size_t)bn * KP + k] = v;
}

// ======= weight packs ========================================================
__global__ void pack_split_kernel(const float* __restrict__ W, __half* __restrict__ Wp,
                                  int K, int KP) {
    int k = blockIdx.x * blockDim.x + threadIdx.x;
    int r = blockIdx.y;
    if (k >= KP) return;
    float v = (k < K) ? W[(size_t)r * K + k] : 0.0f;
    __half hi = __float2half_rn(v);
    __half lo = __float2half_rn(v - __half2float(hi));
    size_t base = (size_t)r * (2 * (size_t)KP);
    Wp[base + k] = hi;
    Wp[base + KP + k] = lo;
}
__global__ void pack_hi_kernel(const float* __restrict__ W, __half* __restrict__ Wp,
                               int K, int KP) {
    int k = blockIdx.x * blockDim.x + threadIdx.x;
    int r = blockIdx.y;
    if (k >= KP) return;
    float v = (k < K) ? W[(size_t)r * K + k] : 0.0f;
    Wp[(size_t)r * KP + k] = __float2half_rn(v);
}

// =================== host side ==============================================
extern "C" void kernel_launch(void* const* d_in, const int* in_sizes, int n_in,
                              void* d_out, int out_size) {
    const float* x   = (const float*)d_in[0];
    const float* ws1 = (const float*)d_in[1];
    const float* bs1 = (const float*)d_in[2];
    const float* W1  = (const float*)d_in[3];
    const float* b1  = (const float*)d_in[4];
    const float* ws2 = (const float*)d_in[5];
    const float* bs2 = (const float*)d_in[6];
    const float* W2  = (const float*)d_in[7];
    const float* b2  = (const float*)d_in[8];
    float* out = (float*)d_out;

    float *scores1, *scores2;
    __half *x1, *h, *h2, *W1p, *W2p;
    int *idx1, *idx2;
    cudaGetSymbolAddress((void**)&scores1, g_scores1);
    cudaGetSymbolAddress((void**)&idx1,    g_idx1);
    cudaGetSymbolAddress((void**)&x1,      g_x1);
    cudaGetSymbolAddress((void**)&h,       g_h);
    cudaGetSymbolAddress((void**)&scores2, g_scores2);
    cudaGetSymbolAddress((void**)&idx2,    g_idx2);
    cudaGetSymbolAddress((void**)&h2,      g_h2);
    cudaGetSymbolAddress((void**)&W1p,     g_W1p);
    cudaGetSymbolAddress((void**)&W2p,     g_W2p);

    cudaFuncSetAttribute(gemm_hmma<0>, cudaFuncAttributeMaxDynamicSharedMemorySize, GEMM_SMEM);
    cudaFuncSetAttribute(gemm_hmma<1>, cudaFuncAttributeMaxDynamicSharedMemorySize, GEMM_SMEM);

    // weight packs
    pack_split_kernel<<<dim3((K1P + 255) / 256, H_), 256>>>(W1, W1p, K1_, K1P);
    pack_hi_kernel<<<dim3((K2P + 255) / 256, D_), 256>>>(W2, W2p, K2_, K2P);

    // stage 1: prune x (D -> K1)
    scores_kernel<<<dim3(D_ / 256, B_), 256>>>(x, ws1, bs1, scores1, D_);
    topk_kernel<D_, K1_, K1P><<<B_, 1024>>>(scores1, idx1);
    gather1_kernel<<<dim3((K1P + 255) / 256, B_ * N_), 256>>>(x, idx1, x1, D_, K1_, K1P);

    // net1 (3-term fp16) + fused relu/scores2/half-store
    gemm_hmma<1><<<dim3(H_ / 256, (B_ * N_) / 128), 256, GEMM_SMEM>>>(
        x1, W1p, b1, nullptr, h, scores2, ws2, bs2,
        H_, KCH1, NCK1, 1, 2 * K1P, 2 * K1P);

    // stage 2: prune h (H -> K2)
    topk_kernel<H_, K2_, K2P><<<B_, 1024>>>(scores2, idx2);
    gather2_kernel<<<dim3((K2P + 255) / 256, B_ * N_), 256>>>(h, idx2, h2, H_, K2_, K2P);

    // net2 (1-term fp16): out = h2 @ W2^T + b2
    gemm_hmma<0><<<dim3(D_ / 256, (B_ * N_) / 128), 256, GEMM_SMEM>>>(
        h2, W2p, b2, out, nullptr, nullptr, nullptr, nullptr,
        D_, KCH2, NCK2, 0, K2P, K2P);
}

// round 10
// speedup vs baseline: 3.3297x; 1.1178x over previous
#include <cuda_runtime.h>
#include <cuda_fp16.h>
#include <cstdint>

// Problem dims
#define B_  256
#define N_  128
#define D_  1024
#define H_  4096
#define K1_ 819
#define K2_ 3276
#define K1P 832                 // padded keep-counts (multiple of 64)
#define K2P 3328
#define NCK1 (K1P/64)           // 13 chunk-cols per section
#define NCK2 (K2P/64)           // 52
#define KCH1 (3*NCK1)           // 39 total K-chunks (3-term GEMM1)
#define KCH2 NCK2               // 52 (1-term GEMM2)

// ---------------- scratch (device globals; no allocation allowed) ----------
__device__ __align__(256) float  g_scores1[B_ * D_];
__device__ __align__(256) int    g_idx1[B_ * K1P];
__device__ __align__(256) __half g_x1[(size_t)B_ * N_ * 2 * K1P];  // [hi|lo]
__device__ __align__(256) __half g_h[(size_t)B_ * N_ * H_];        // hi plane
__device__ __align__(256) float  g_scores2[B_ * H_];
__device__ __align__(256) int    g_idx2[B_ * K2P];
__device__ __align__(256) __half g_h2[(size_t)B_ * N_ * K2P];      // hi only
__device__ __align__(256) __half g_W1p[(size_t)H_ * 2 * K1P];      // [hi|lo]
__device__ __align__(256) __half g_W2p[(size_t)D_ * K2P];          // hi only

// =================== helpers ================================================
__device__ __forceinline__ uint32_t smem_u32(const void* p) {
    uint32_t a;
    asm("{ .reg .u64 t; cvta.to.shared.u64 t, %1; cvt.u32.u64 %0, t; }" : "=r"(a) : "l"(p));
    return a;
}
__device__ __forceinline__ void cp16(uint32_t dst, const void* src) {
    asm volatile("cp.async.cg.shared.global [%0], [%1], 16;" :: "r"(dst), "l"(src) : "memory");
}
__device__ __forceinline__ uint32_t swz(uint32_t off) { return off ^ ((off >> 3) & 0x70); }

#define LDSM_X4(r, addr) \
    asm volatile("ldmatrix.sync.aligned.m8n8.x4.shared.b16 {%0,%1,%2,%3}, [%4];" \
        : "=r"((r)[0]), "=r"((r)[1]), "=r"((r)[2]), "=r"((r)[3]) : "r"(addr))

#define MMA16816(c, a, b) \
    asm volatile("mma.sync.aligned.m16n8k16.row.col.f32.f16.f16.f32 " \
        "{%0,%1,%2,%3}, {%4,%5,%6,%7}, {%8,%9}, {%0,%1,%2,%3};" \
        : "+f"((c)[0]), "+f"((c)[1]), "+f"((c)[2]), "+f"((c)[3]) \
        : "r"((a)[0]), "r"((a)[1]), "r"((a)[2]), "r"((a)[3]), "r"((b)[0]), "r"((b)[1]))

// =================== fp16 HMMA GEMM, 128(M)x256(N)x64 tiles ================
// (unchanged from R9 — at legacy-HMMA pipe roofline)
#define STAGES 4
#define STAGE_BYTES 49152       // (128+256) rows x 128B
#define ATILE 16384
#define GEMM_SMEM (STAGES * STAGE_BYTES)   // 192 KB

template <int EPI>
__global__ __launch_bounds__(256, 1) void gemm_hmma(
    const __half* __restrict__ A, const __half* __restrict__ Bw,
    const float* __restrict__ bias, float* __restrict__ Cout,
    __half* __restrict__ Hout, float* __restrict__ scores_out,
    const float* __restrict__ ws2, const float* __restrict__ bs2,
    int Nd, int kchunks, int ncol, int mode, int kstA, int kstB)
{
    extern __shared__ char smem[];
    const uint32_t sbase = smem_u32(smem);
    const int tid = threadIdx.x, wid = tid >> 5, lane = tid & 31;
    const int m0 = blockIdx.y * 128, n0 = blockIdx.x * 256;
    const int wm = (wid >> 2) * 64, wn = (wid & 3) * 64;

    float c[4][8][4];
#pragma unroll
    for (int i = 0; i < 4; i++)
#pragma unroll
        for (int j = 0; j < 8; j++)
#pragma unroll
            for (int q = 0; q < 4; q++) c[i][j][q] = 0.0f;

    const int lr = tid >> 3;
    const int lcb = (tid & 7) * 16;
    const int arow = wm + (lane & 15);
    const int brow = wn + (lane & 15);
    const int csel = (lane >> 4) << 4;

#define LOAD_CHUNK(k) do { \
    int _ka, _kb; \
    if (mode == 1) { \
        int _t = (k) / ncol, _kk = (k) - _t * ncol; \
        _ka = (_t == 2) ? ncol + _kk : _kk; \
        _kb = (_t == 1) ? ncol + _kk : _kk; \
    } else { _ka = (k); _kb = (k); } \
    int _s = (k) & (STAGES - 1); \
    uint32_t _as = sbase + _s * STAGE_BYTES; \
    uint32_t _bs = _as + ATILE; \
    const char* _Ag = (const char*)A + (size_t)_ka * 128 + lcb + (size_t)(m0 + lr) * (size_t)kstA * 2; \
    const char* _Bg = (const char*)Bw + (size_t)_kb * 128 + lcb + (size_t)(n0 + lr) * (size_t)kstB * 2; \
    uint32_t _d = swz((uint32_t)(lr * 128 + lcb)); \
    size_t _ra = (size_t)kstA * 64, _rb = (size_t)kstB * 64; \
    _Pragma("unroll") \
    for (int _w = 0; _w < 4; _w++) cp16(_as + _d + _w * 0x1000, _Ag + _w * _ra); \
    _Pragma("unroll") \
    for (int _w = 0; _w < 8; _w++) cp16(_bs + _d + _w * 0x1000, _Bg + _w * _rb); \
} while (0)

#define LOAD_FRAGS(ks, a, b) do { \
    const int _cb = (ks) * 32 + csel; \
    _Pragma("unroll") \
    for (int _mt = 0; _mt < 4; _mt++) { \
        uint32_t _off = (uint32_t)((arow + _mt * 16) * 128 + _cb); \
        LDSM_X4((a)[_mt], as + swz(_off)); \
    } \
    _Pragma("unroll") \
    for (int _p = 0; _p < 4; _p++) { \
        uint32_t _t4[4]; \
        uint32_t _off = (uint32_t)((brow + _p * 16) * 128 + _cb); \
        LDSM_X4(_t4, bs + swz(_off)); \
        (b)[2 * _p][0] = _t4[0]; (b)[2 * _p][1] = _t4[2]; \
        (b)[2 * _p + 1][0] = _t4[1]; (b)[2 * _p + 1][1] = _t4[3]; \
    } \
} while (0)

#define DO_MMAS(a, b) do { \
    _Pragma("unroll") \
    for (int _mt = 0; _mt < 4; _mt++) \
        _Pragma("unroll") \
        for (int _nt = 0; _nt < 8; _nt++) \
            MMA16816(c[_mt][_nt], (a)[_mt], (b)[_nt]); \
} while (0)

    for (int k = 0; k < STAGES - 1 && k < kchunks; k++) {
        LOAD_CHUNK(k);
        asm volatile("cp.async.commit_group;" ::: "memory");
    }

    for (int k = 0; k < kchunks; k++) {
        asm volatile("cp.async.wait_group %0;" :: "n"(STAGES - 2) : "memory");
        __syncthreads();

        const int st = k & (STAGES - 1);
        const uint32_t as = sbase + st * STAGE_BYTES;
        const uint32_t bs = as + ATILE;

        uint32_t a0[4][4], b0[8][2], a1[4][4], b1[8][2];
        LOAD_FRAGS(0, a0, b0);

        if (k + STAGES - 1 < kchunks) LOAD_CHUNK(k + STAGES - 1);
        asm volatile("cp.async.commit_group;" ::: "memory");

        LOAD_FRAGS(1, a1, b1);
        DO_MMAS(a0, b0);
        LOAD_FRAGS(2, a0, b0);
        DO_MMAS(a1, b1);
        LOAD_FRAGS(3, a1, b1);
        DO_MMAS(a0, b0);
        DO_MMAS(a1, b1);
    }

    if (EPI == 0) {
#pragma unroll
        for (int mt = 0; mt < 4; mt++) {
            int row = m0 + wm + mt * 16 + (lane >> 2);
#pragma unroll
            for (int nt = 0; nt < 8; nt++) {
                int col = n0 + wn + nt * 8 + 2 * (lane & 3);
                float2 bv = *(const float2*)(bias + col);
                float2 v0 = make_float2(c[mt][nt][0] + bv.x, c[mt][nt][1] + bv.y);
                float2 v1 = make_float2(c[mt][nt][2] + bv.x, c[mt][nt][3] + bv.y);
                *(float2*)(Cout + (size_t)row * Nd + col) = v0;
                *(float2*)(Cout + (size_t)(row + 8) * Nd + col) = v1;
            }
        }
    } else {
        asm volatile("cp.async.wait_group 0;" ::: "memory");
        __syncthreads();
        float* ssm = (float*)smem;
        ssm[tid] = 0.0f;
        __syncthreads();

        float sacc[16];
#pragma unroll
        for (int q = 0; q < 16; q++) sacc[q] = 0.0f;

#pragma unroll
        for (int mt = 0; mt < 4; mt++) {
            int r0 = wm + mt * 16 + (lane >> 2);
            int r1 = r0 + 8;
            float w0 = ws2[r0], w1 = ws2[r1];
#pragma unroll
            for (int nt = 0; nt < 8; nt++) {
                int col = wn + nt * 8 + 2 * (lane & 3);
                float2 bv = *(const float2*)(bias + n0 + col);
                float v0x = fmaxf(c[mt][nt][0] + bv.x, 0.0f);
                float v0y = fmaxf(c[mt][nt][1] + bv.y, 0.0f);
                float v1x = fmaxf(c[mt][nt][2] + bv.x, 0.0f);
                float v1y = fmaxf(c[mt][nt][3] + bv.y, 0.0f);
                *(__half2*)(Hout + (size_t)(m0 + r0) * Nd + n0 + col) = __floats2half2_rn(v0x, v0y);
                *(__half2*)(Hout + (size_t)(m0 + r1) * Nd + n0 + col) = __floats2half2_rn(v1x, v1y);
                sacc[nt * 2 + 0] += w0 * v0x + w1 * v1x;
                sacc[nt * 2 + 1] += w0 * v0y + w1 * v1y;
            }
        }
#pragma unroll
        for (int nt = 0; nt < 8; nt++) {
            int col = wn + nt * 8 + 2 * (lane & 3);
            atomicAdd(&ssm[col], sacc[nt * 2 + 0]);
            atomicAdd(&ssm[col + 1], sacc[nt * 2 + 1]);
        }
        __syncthreads();
        scores_out[(size_t)blockIdx.y * Nd + n0 + tid] = ssm[tid] + bs2[0];
    }
}

// =================== scores1: s[b,c] = sum_n x[b,n,c]*ws[n] + bs ============
__global__ void scores_kernel(const float* __restrict__ x, const float* __restrict__ ws,
                              const float* __restrict__ bs, float* __restrict__ out, int C) {
    __shared__ float w[N_];
    int tid = threadIdx.x;
    if (tid < N_) w[tid] = ws[tid];
    __syncthreads();
    int c = blockIdx.x * blockDim.x + tid;
    int b = blockIdx.y;
    const float* xp = x + (size_t)b * N_ * C + c;
    float s = 0.0f;
#pragma unroll 8
    for (int n = 0; n < N_; n++) s += xp[(size_t)n * C] * w[n];
    out[(size_t)b * C + c] = s + bs[0];
}

// ====== top-k via MSB radix select (jax.lax.top_k tie semantics) ============
// Keeps the KKEEP largest; ties at threshold resolved lowest-index-first.
// Output: ascending original indices (order-preserving compaction).
template <int C, int KKEEP, int KPAD>
__global__ __launch_bounds__(256) void topk_radix(const float* __restrict__ scores,
                                                  int* __restrict__ idx_out) {
    constexpr int E = C / 256;
    __shared__ uint32_t key[C];
    __shared__ int hist[256];
    __shared__ int scn[256];
    __shared__ int s_byte, s_rem;

    int b = blockIdx.x, tid = threadIdx.x;

    // load + orderable-key transform (ascending uint == ascending float)
#pragma unroll
    for (int e = 0; e < E; e++) {
        int i = tid * E + e;
        uint32_t u = __float_as_uint(scores[(size_t)b * C + i]);
        key[i] = (u & 0x80000000u) ? ~u : (u | 0x80000000u);
    }
    __syncthreads();

    // 4 MSB-first radix passes to find the threshold key
    uint32_t prefix = 0;
    int rem = KKEEP;
#pragma unroll
    for (int pass = 0; pass < 4; pass++) {
        int shift = 24 - 8 * pass;
        hist[tid] = 0;
        __syncthreads();
#pragma unroll
        for (int e = 0; e < E; e++) {
            uint32_t u = key[tid * E + e];
            bool in = (pass == 0) || ((u >> (shift + 8)) == prefix);
            if (in) atomicAdd(&hist[(u >> shift) & 0xFF], 1);
        }
        __syncthreads();
        // inclusive suffix sum: scn[t] = sum_{j>=t} hist[j]
        scn[tid] = hist[tid];
        __syncthreads();
        for (int off = 1; off < 256; off <<= 1) {
            int v = (tid + off < 256) ? scn[tid + off] : 0;
            __syncthreads();
            scn[tid] += v;
            __syncthreads();
        }
        int sgt = (tid < 255) ? scn[tid + 1] : 0;     // count strictly-greater bytes
        if (sgt < rem && sgt + hist[tid] >= rem) {    // unique crossing bin
            s_byte = tid;
            s_rem = rem - sgt;
        }
        __syncthreads();
        prefix = (prefix << 8) | (uint32_t)s_byte;
        rem = s_rem;
        __syncthreads();
    }
    const uint32_t thr = prefix;    // exact 32-bit threshold key
    const int need = rem;           // how many ==thr to keep (lowest indices win)

    // exclusive rank among equals (element order == index order)
    int eqc = 0;
#pragma unroll
    for (int e = 0; e < E; e++) eqc += (key[tid * E + e] == thr);
    scn[tid] = eqc;
    __syncthreads();
    for (int off = 1; off < 256; off <<= 1) {
        int v = (tid >= off) ? scn[tid - off] : 0;
        __syncthreads();
        scn[tid] += v;
        __syncthreads();
    }
    int er = scn[tid] - eqc;

    // keep flags + count
    int kc = 0;
    unsigned keepmask = 0;
#pragma unroll
    for (int e = 0; e < E; e++) {
        uint32_t u = key[tid * E + e];
        bool kp = (u > thr) || (u == thr && er < need);
        if (u == thr) er++;
        if (kp) { keepmask |= (1u << e); kc++; }
    }
    __syncthreads();
    scn[tid] = kc;
    __syncthreads();
    for (int off = 1; off < 256; off <<= 1) {
        int v = (tid >= off) ? scn[tid - off] : 0;
        __syncthreads();
        scn[tid] += v;
        __syncthreads();
    }
    int wbase = scn[tid] - kc;
#pragma unroll
    for (int e = 0; e < E; e++)
        if (keepmask & (1u << e))
            idx_out[(size_t)b * KPAD + (wbase++)] = tid * E + e;
}

// ======= gather1: fp32 -> fp16 [hi | lo] sections, 4 k per thread ===========
__global__ void gather1_kernel(const float* __restrict__ src, const int* __restrict__ idx,
                               __half* __restrict__ dst, int C, int KKEEP, int KP) {
    int k4 = (blockIdx.x * blockDim.x + threadIdx.x) * 4;
    int bn = blockIdx.y;
    int b = bn >> 7;
    if (k4 >= KP) return;
    float v[4];
#pragma unroll
    for (int j = 0; j < 4; j++) {
        int kk = k4 + j;
        v[j] = (kk < KKEEP) ? src[(size_t)bn * C + idx[(size_t)b * KP + kk]] : 0.0f;
    }
    __half2 hi0 = __floats2half2_rn(v[0], v[1]);
    __half2 hi1 = __floats2half2_rn(v[2], v[3]);
    __half2 lo0 = __floats2half2_rn(v[0] - __half2float(__low2half(hi0)),
                                    v[1] - __half2float(__high2half(hi0)));
    __half2 lo1 = __floats2half2_rn(v[2] - __half2float(__low2half(hi1)),
                                    v[3] - __half2float(__high2half(hi1)));
    size_t base = (size_t)bn * (2 * (size_t)KP);
    *(__half2*)(dst + base + k4)          = hi0;
    *(__half2*)(dst + base + k4 + 2)      = hi1;
    *(__half2*)(dst + base + KP + k4)     = lo0;
    *(__half2*)(dst + base + KP + k4 + 2) = lo1;
}

// ======= gather2: fp16 h (hi plane) -> h2, 4 k per thread ===================
__global__ void gather2_kernel(const __half* __restrict__ src, const int* __restrict__ idx,
                               __half* __restrict__ dst, int C, int KKEEP, int KP) {
    int k4 = (blockIdx.x * blockDim.x + threadIdx.x) * 4;
    int bn = blockIdx.y;
    int b = bn >> 7;
    if (k4 >= KP) return;
    __half v[4];
#pragma unroll
    for (int j = 0; j < 4; j++) {
        int kk = k4 + j;
        v[j] = (kk < KKEEP) ? src[(size_t)bn * C + idx[(size_t)b * KP + kk]]
                            : __ushort_as_half((unsigned short)0);
    }
    *(__half2*)(dst + (size_t)bn * KP + k4)     = __halves2half2(v[0], v[1]);
    *(__half2*)(dst + (size_t)bn * KP + k4 + 2) = __halves2half2(v[2], v[3]);
}

// ======= weight packs ========================================================
__global__ void pack_split_kernel(const float* __restrict__ W, __half* __restrict__ Wp,
                                  int K, int KP) {
    int k = blockIdx.x * blockDim.x + threadIdx.x;
    int r = blockIdx.y;
    if (k >= KP) return;
    float v = (k < K) ? W[(size_t)r * K + k] : 0.0f;
    __half hi = __float2half_rn(v);
    __half lo = __float2half_rn(v - __half2float(hi));
    size_t base = (size_t)r * (2 * (size_t)KP);
    Wp[base + k] = hi;
    Wp[base + KP + k] = lo;
}
__global__ void pack_hi_kernel(const float* __restrict__ W, __half* __restrict__ Wp,
                               int K, int KP) {
    int k = blockIdx.x * blockDim.x + threadIdx.x;
    int r = blockIdx.y;
    if (k >= KP) return;
    float v = (k < K) ? W[(size_t)r * K + k] : 0.0f;
    Wp[(size_t)r * KP + k] = __float2half_rn(v);
}

// =================== host side ==============================================
extern "C" void kernel_launch(void* const* d_in, const int* in_sizes, int n_in,
                              void* d_out, int out_size) {
    const float* x   = (const float*)d_in[0];
    const float* ws1 = (const float*)d_in[1];
    const float* bs1 = (const float*)d_in[2];
    const float* W1  = (const float*)d_in[3];
    const float* b1  = (const float*)d_in[4];
    const float* ws2 = (const float*)d_in[5];
    const float* bs2 = (const float*)d_in[6];
    const float* W2  = (const float*)d_in[7];
    const float* b2  = (const float*)d_in[8];
    float* out = (float*)d_out;

    float *scores1, *scores2;
    __half *x1, *h, *h2, *W1p, *W2p;
    int *idx1, *idx2;
    cudaGetSymbolAddress((void**)&scores1, g_scores1);
    cudaGetSymbolAddress((void**)&idx1,    g_idx1);
    cudaGetSymbolAddress((void**)&x1,      g_x1);
    cudaGetSymbolAddress((void**)&h,       g_h);
    cudaGetSymbolAddress((void**)&scores2, g_scores2);
    cudaGetSymbolAddress((void**)&idx2,    g_idx2);
    cudaGetSymbolAddress((void**)&h2,      g_h2);
    cudaGetSymbolAddress((void**)&W1p,     g_W1p);
    cudaGetSymbolAddress((void**)&W2p,     g_W2p);

    cudaFuncSetAttribute(gemm_hmma<0>, cudaFuncAttributeMaxDynamicSharedMemorySize, GEMM_SMEM);
    cudaFuncSetAttribute(gemm_hmma<1>, cudaFuncAttributeMaxDynamicSharedMemorySize, GEMM_SMEM);

    // weight packs
    pack_split_kernel<<<dim3((K1P + 255) / 256, H_), 256>>>(W1, W1p, K1_, K1P);
    pack_hi_kernel<<<dim3((K2P + 255) / 256, D_), 256>>>(W2, W2p, K2_, K2P);

    // stage 1: prune x (D -> K1)
    scores_kernel<<<dim3(D_ / 256, B_), 256>>>(x, ws1, bs1, scores1, D_);
    topk_radix<D_, K1_, K1P><<<B_, 256>>>(scores1, idx1);
    gather1_kernel<<<dim3((K1P / 4 + 255) / 256, B_ * N_), 256>>>(x, idx1, x1, D_, K1_, K1P);

    // net1 (3-term fp16) + fused relu/scores2/half-store
    gemm_hmma<1><<<dim3(H_ / 256, (B_ * N_) / 128), 256, GEMM_SMEM>>>(
        x1, W1p, b1, nullptr, h, scores2, ws2, bs2,
        H_, KCH1, NCK1, 1, 2 * K1P, 2 * K1P);

    // stage 2: prune h (H -> K2)
    topk_radix<H_, K2_, K2P><<<B_, 256>>>(scores2, idx2);
    gather2_kernel<<<dim3((K2P / 4 + 255) / 256, B_ * N_), 256>>>(h, idx2, h2, H_, K2_, K2P);

    // net2 (1-term fp16): out = h2 @ W2^T + b2
    gemm_hmma<0><<<dim3(D_ / 256, (B_ * N_) / 128), 256, GEMM_SMEM>>>(
        h2, W2p, b2, out, nullptr, nullptr, nullptr, nullptr,
        D_, KCH2, NCK2, 0, K2P, K2P);
}